// round 8
// baseline (speedup 1.0000x reference)
#include <cuda_runtime.h>
#include <cuda_bf16.h>
#include <math.h>

// Problem constants
#define BB 2
#define II 768
#define CA 768
#define CS 384
#define CZ 128
#define HH 16
#define DD 48
#define HC 768
#define ROWS (BB*II)          // 1536
#define EPS 1e-5f
#define PS 772                // padded p-row stride in attn kernel

// ---------------- device scratch (no allocations allowed) ----------------
__device__ float g_aln  [ROWS*CA];
__device__ float g_sln  [ROWS*CS];
__device__ float g_t1   [ROWS*CA];
__device__ float g_t2   [ROWS*CA];
__device__ float g_a2   [ROWS*CA];
__device__ float g_q    [ROWS*HC];
__device__ float g_k    [ROWS*HC];
__device__ float g_v    [ROWS*HC];
__device__ float g_gbuf [ROWS*HC];
__device__ float g_gate [ROWS*CA];
__device__ float g_scores[(size_t)BB*HH*II*II];   // [b][h][i][j]  ~75.5 MB
__device__ float g_o    [ROWS*HC];

// ---------------- tf32 helpers ----------------
__device__ __forceinline__ unsigned f2tf(float x) {
    unsigned u;
    asm("cvt.rna.tf32.f32 %0, %1;" : "=r"(u) : "f"(x));
    return u;
}
__device__ __forceinline__ float tf32r(float x) {
    return __uint_as_float(f2tf(x));
}

__device__ __forceinline__ void mma_tf32(float* d, const unsigned* a, const unsigned* b) {
    asm volatile(
        "mma.sync.aligned.m16n8k8.row.col.f32.tf32.tf32.f32 "
        "{%0,%1,%2,%3}, {%4,%5,%6,%7}, {%8,%9}, {%0,%1,%2,%3};"
        : "+f"(d[0]), "+f"(d[1]), "+f"(d[2]), "+f"(d[3])
        : "r"(a[0]), "r"(a[1]), "r"(a[2]), "r"(a[3]), "r"(b[0]), "r"(b[1]));
}

// One 8-deep K slice for gemm_tc ([k][m] A layout, [k][n] B layout)
template<int SA, int SB>
__device__ __forceinline__ void do_mma8(const float* AhP, const float* AlP,
                                        const float* BhP, const float* BlP,
                                        int kk, int wm, int wn, int l4, int g,
                                        float acc[2][4][4])
{
    unsigned ah[2][4], al[2][4], bh[4][2], bl[4][2];
    const float* r0 = AhP + (kk + l4) * SA;
    const float* r1 = AhP + (kk + l4 + 4) * SA;
    const float* s0 = AlP + (kk + l4) * SA;
    const float* s1 = AlP + (kk + l4 + 4) * SA;
    #pragma unroll
    for (int mt = 0; mt < 2; mt++) {
        int mm = wm + mt * 16;
        ah[mt][0] = __float_as_uint(r0[mm + g]);
        ah[mt][1] = __float_as_uint(r0[mm + g + 8]);
        ah[mt][2] = __float_as_uint(r1[mm + g]);
        ah[mt][3] = __float_as_uint(r1[mm + g + 8]);
        al[mt][0] = __float_as_uint(s0[mm + g]);
        al[mt][1] = __float_as_uint(s0[mm + g + 8]);
        al[mt][2] = __float_as_uint(s1[mm + g]);
        al[mt][3] = __float_as_uint(s1[mm + g + 8]);
    }
    const float* t0 = BhP + (kk + l4) * SB;
    const float* t1 = BhP + (kk + l4 + 4) * SB;
    const float* u0 = BlP + (kk + l4) * SB;
    const float* u1 = BlP + (kk + l4 + 4) * SB;
    #pragma unroll
    for (int nt = 0; nt < 4; nt++) {
        int nn = wn + nt * 8 + g;
        bh[nt][0] = __float_as_uint(t0[nn]);
        bh[nt][1] = __float_as_uint(t1[nn]);
        bl[nt][0] = __float_as_uint(u0[nn]);
        bl[nt][1] = __float_as_uint(u1[nn]);
    }
    #pragma unroll
    for (int mt = 0; mt < 2; mt++)
        #pragma unroll
        for (int nt = 0; nt < 4; nt++) {
            mma_tf32(acc[mt][nt], ah[mt], bh[nt]);
            mma_tf32(acc[mt][nt], ah[mt], bl[nt]);
            mma_tf32(acc[mt][nt], al[mt], bh[nt]);
        }
}

// ---------------- LayerNorm over rows ----------------
__global__ void ln_kernel(const float* __restrict__ x,
                          const float* __restrict__ w,
                          const float* __restrict__ b,
                          float* __restrict__ y, int C)
{
    int row = blockIdx.x;
    const float* xr = x + (size_t)row * C;
    float s1 = 0.f, s2 = 0.f;
    for (int c = threadIdx.x; c < C; c += blockDim.x) {
        float v = xr[c]; s1 += v; s2 += v * v;
    }
    __shared__ float red[64];
    #pragma unroll
    for (int o = 16; o; o >>= 1) {
        s1 += __shfl_xor_sync(0xffffffffu, s1, o);
        s2 += __shfl_xor_sync(0xffffffffu, s2, o);
    }
    int wid = threadIdx.x >> 5, lid = threadIdx.x & 31;
    if (lid == 0) { red[wid] = s1; red[wid + 32] = s2; }
    __syncthreads();
    if (wid == 0) {
        s1 = (lid < (blockDim.x >> 5)) ? red[lid] : 0.f;
        s2 = (lid < (blockDim.x >> 5)) ? red[lid + 32] : 0.f;
        #pragma unroll
        for (int o = 16; o; o >>= 1) {
            s1 += __shfl_xor_sync(0xffffffffu, s1, o);
            s2 += __shfl_xor_sync(0xffffffffu, s2, o);
        }
        if (lid == 0) { red[0] = s1; red[1] = s2; }
    }
    __syncthreads();
    float mean = red[0] / C;
    float var  = red[1] / C - mean * mean;
    float rs   = rsqrtf(var + EPS);
    float* yr = y + (size_t)row * C;
    for (int c = threadIdx.x; c < C; c += blockDim.x) {
        float v = (xr[c] - mean) * rs;
        if (w) v = v * w[c] + b[c];
        yr[c] = v;
    }
}

// ---------------- tf32 tensor-core GEMM, batched over blockIdx.z ----------
struct GemmJob { const float* W; const float* bias; const float* mul; float* out; int sig; };
struct GemmBatch { GemmJob j[4]; };

// C = A[M,K] @ W[K,N]; tile 128x64, 256 threads (8 warps, 4x2), warp tile 32x32.
// Double-buffered smem, single __syncthreads per K-tile.
__global__ void __launch_bounds__(256)
gemm_tc_kernel(const float* __restrict__ A, GemmBatch batch, int M, int N, int K)
{
    __shared__ float Ah[2][16][136], Al[2][16][136];
    __shared__ float Bh[2][16][72],  Bl[2][16][72];

    GemmJob jb = batch.j[blockIdx.z];
    const float* __restrict__ W = jb.W;

    int t = threadIdx.x;
    int m0 = blockIdx.y * 128, n0 = blockIdx.x * 64;
    int w = t >> 5, lane = t & 31;
    int wm = (w >> 1) * 32, wn = (w & 1) * 32;
    int l4 = lane & 3, g = lane >> 2;

    int am = t >> 1, ak = (t & 1) * 8;
    int bk = t >> 4, bn = (t & 15) * 4;
    const float* Ap = A + (size_t)(m0 + am) * K + ak;
    const float* Wp = W + (size_t)bk * N + n0 + bn;

    float acc[2][4][4] = {};
    int nkt = K >> 4;

    float4 a0 = *(const float4*)Ap;
    float4 a1 = *(const float4*)(Ap + 4);
    float4 b0 = *(const float4*)Wp;

    for (int kt = 0; kt < nkt; kt++) {
        int p = kt & 1;
        {   // hi/lo split + store current tile into buffer p
            float av[8] = {a0.x,a0.y,a0.z,a0.w,a1.x,a1.y,a1.z,a1.w};
            #pragma unroll
            for (int u = 0; u < 8; u++) {
                float hi = tf32r(av[u]);
                Ah[p][ak + u][am] = hi;
                Al[p][ak + u][am] = tf32r(av[u] - hi);
            }
            float bv[4] = {b0.x, b0.y, b0.z, b0.w};
            float h0 = tf32r(bv[0]), h1 = tf32r(bv[1]);
            float h2 = tf32r(bv[2]), h3 = tf32r(bv[3]);
            *(float4*)&Bh[p][bk][bn] = make_float4(h0, h1, h2, h3);
            *(float4*)&Bl[p][bk][bn] = make_float4(tf32r(bv[0]-h0), tf32r(bv[1]-h1),
                                                   tf32r(bv[2]-h2), tf32r(bv[3]-h3));
        }
        __syncthreads();
        if (kt + 1 < nkt) {     // prefetch next tile (overlaps mma)
            const float* Ap2 = Ap + (size_t)(kt + 1) * 16;
            a0 = *(const float4*)Ap2;
            a1 = *(const float4*)(Ap2 + 4);
            b0 = *(const float4*)(Wp + (size_t)(kt + 1) * 16 * N);
        }
        do_mma8<136, 72>(&Ah[p][0][0], &Al[p][0][0], &Bh[p][0][0], &Bl[p][0][0], 0, wm, wn, l4, g, acc);
        do_mma8<136, 72>(&Ah[p][0][0], &Al[p][0][0], &Bh[p][0][0], &Bl[p][0][0], 8, wm, wn, l4, g, acc);
    }

    // epilogue
    const float* bias = jb.bias;
    const float* mul  = jb.mul;
    float* out = jb.out;
    int sig = jb.sig;
    #pragma unroll
    for (int mt = 0; mt < 2; mt++)
        #pragma unroll
        for (int nt = 0; nt < 4; nt++) {
            int n = n0 + wn + nt * 8 + l4 * 2;
            float bx = 0.f, by = 0.f;
            if (bias) { bx = bias[n]; by = bias[n + 1]; }
            #pragma unroll
            for (int half = 0; half < 2; half++) {
                int m = m0 + wm + mt * 16 + g + half * 8;
                float x = acc[mt][nt][half * 2]     + bx;
                float y = acc[mt][nt][half * 2 + 1] + by;
                if (sig) {
                    x = 1.f / (1.f + expf(-x));
                    y = 1.f / (1.f + expf(-y));
                }
                if (mul) {
                    float2 mv = *(const float2*)&mul[(size_t)m * N + n];
                    x *= mv.x; y *= mv.y;
                }
                *(float2*)&out[(size_t)m * N + n] = make_float2(x, y);
            }
        }
}

// ---------------- elementwise ----------------
__global__ void adaln_ew_kernel(const float* __restrict__ t1,
                                const float* __restrict__ t2,
                                const float* __restrict__ aln,
                                float* __restrict__ a2, int n)
{
    int i = blockIdx.x * blockDim.x + threadIdx.x;
    if (i < n) {
        float s = 1.f / (1.f + expf(-t1[i]));
        a2[i] = s * aln[i] + t2[i];
    }
}

// ---------------- pair bias (tensor core): scores = LN(z)@Wb + beta --------
// Block: 64 j-rows for fixed (b,i). 256 threads = 8 warps (4 m-tiles x 2 n-tiles).
__global__ void __launch_bounds__(256)
pairbias_tc_kernel(const float* __restrict__ z,
                   const float* __restrict__ beta,
                   const float* __restrict__ lnb_w,
                   const float* __restrict__ lnb_b,
                   const float* __restrict__ Wb,
                   float* __restrict__ scores)
{
    __shared__ __align__(16) float zt[64][132];    // raw z tile, row-major
    __shared__ float wbh[128][24], wbl[128][24];   // [c][h] hi/lo of lnb_w*Wb
    __shared__ float bt[64][17];                   // beta tile
    __shared__ float colsum[16], consth[16];
    __shared__ float mean_s[64], rs_s[64];
    __shared__ float ps1[64][4], ps2[64][4];

    int t  = threadIdx.x;
    int j0 = blockIdx.x * 64;
    int bi = blockIdx.y;
    int b  = bi / II, i = bi % II;

    // stage wb hi/lo
    for (int e = t; e < 128 * 16; e += 256) {
        int c = e >> 4, h = e & 15;
        float wv = lnb_w[c] * Wb[c * 16 + h];
        float hi = tf32r(wv);
        wbh[c][h] = hi;
        wbl[c][h] = tf32r(wv - hi);
    }
    // stage beta tile
    {
        const float4* bg = (const float4*)(beta + ((size_t)bi * II + j0) * HH);
        float4 v = bg[t];
        int j = t >> 2, h = (t & 3) * 4;
        bt[j][h + 0] = v.x; bt[j][h + 1] = v.y;
        bt[j][h + 2] = v.z; bt[j][h + 3] = v.w;
    }
    // stage z tile (raw)
    {
        const float4* zg = (const float4*)(z + ((size_t)bi * II + j0) * CZ);
        #pragma unroll
        for (int e = t; e < 2048; e += 256) {
            int r = e >> 5, q = e & 31;
            *(float4*)&zt[r][q * 4] = zg[(size_t)r * 32 + q];
        }
    }
    __syncthreads();

    // row-stat partials: 4 threads per row
    {
        int srow = t >> 2, seg = t & 3;
        const float* zr = zt[srow];
        float s1 = 0.f, s2 = 0.f;
        #pragma unroll
        for (int u = 0; u < 32; u++) {
            float v = zr[seg * 32 + u];
            s1 += v; s2 += v * v;
        }
        ps1[srow][seg] = s1; ps2[srow][seg] = s2;
    }
    if (t < 16) {
        float cs = 0.f, ch = 0.f;
        for (int c = 0; c < 128; c++) {
            cs += wbh[c][t] + wbl[c][t];
            ch += lnb_b[c] * Wb[c * 16 + t];
        }
        colsum[t] = cs; consth[t] = ch;
    }
    __syncthreads();
    if (t < 64) {
        float a  = ps1[t][0] + ps1[t][1] + ps1[t][2] + ps1[t][3];
        float b2 = ps2[t][0] + ps2[t][1] + ps2[t][2] + ps2[t][3];
        float m  = a * (1.f / 128.f);
        float var = b2 * (1.f / 128.f) - m * m;
        mean_s[t] = m;
        rs_s[t]   = rsqrtf(var + EPS);
    }

    // mma: dot[j][h] = z_row_j . wb2_col_h   (tf32 3x)
    int w = t >> 5, lane = t & 31, g = lane >> 2, l4 = lane & 3;
    int mb = (w >> 1) * 16, nb = (w & 1) * 8;
    float acc[4] = {0.f, 0.f, 0.f, 0.f};
    #pragma unroll
    for (int ks = 0; ks < 16; ks++) {
        int kk = ks * 8;
        float r0 = zt[mb + g][kk + l4];
        float r1 = zt[mb + g + 8][kk + l4];
        float r2 = zt[mb + g][kk + l4 + 4];
        float r3 = zt[mb + g + 8][kk + l4 + 4];
        unsigned ah[4], al[4];
        ah[0] = f2tf(r0); al[0] = f2tf(r0 - __uint_as_float(ah[0]));
        ah[1] = f2tf(r1); al[1] = f2tf(r1 - __uint_as_float(ah[1]));
        ah[2] = f2tf(r2); al[2] = f2tf(r2 - __uint_as_float(ah[2]));
        ah[3] = f2tf(r3); al[3] = f2tf(r3 - __uint_as_float(ah[3]));
        unsigned bh2[2], bl2[2];
        bh2[0] = __float_as_uint(wbh[kk + l4][nb + g]);
        bh2[1] = __float_as_uint(wbh[kk + l4 + 4][nb + g]);
        bl2[0] = __float_as_uint(wbl[kk + l4][nb + g]);
        bl2[1] = __float_as_uint(wbl[kk + l4 + 4][nb + g]);
        mma_tf32(acc, ah, bh2);
        mma_tf32(acc, ah, bl2);
        mma_tf32(acc, al, bh2);
    }
    __syncthreads();                 // zt reads done; alias as pacc
    float* pacc = &zt[0][0];         // [64][17]
    pacc[(mb + g)     * 17 + nb + 2 * l4]     = acc[0];
    pacc[(mb + g)     * 17 + nb + 2 * l4 + 1] = acc[1];
    pacc[(mb + g + 8) * 17 + nb + 2 * l4]     = acc[2];
    pacc[(mb + g + 8) * 17 + nb + 2 * l4 + 1] = acc[3];
    __syncthreads();

    // epilogue: LN closed form + beta; coalesced score writes
    {
        int j = t & 63, hb = t >> 6;
        float mean = mean_s[j], rs = rs_s[j];
        #pragma unroll
        for (int u = 0; u < 4; u++) {
            int h = hb * 4 + u;
            float v = pacc[j * 17 + h];
            v = rs * (v - mean * colsum[h]) + consth[h] + bt[j][h];
            scores[(((size_t)(b * 16 + h)) * II + i) * II + j0 + j] = v;
        }
    }
}

// ---------------- fused attention: qk (tf32 mma) + softmax + AV + gate -----
// grid: (II/16, B*H). 256 threads. p buffer preloaded with bias from scores.
__global__ void __launch_bounds__(256)
attn_kernel(const float* __restrict__ scores,
            const float* __restrict__ q,
            const float* __restrict__ k,
            const float* __restrict__ v,
            const float* __restrict__ gbuf,
            float* __restrict__ o)
{
    __shared__ __align__(16) float p[16][PS];      // ~49.4KB
    __shared__ __align__(16) float qraw[16][52];   // 3.3KB
    __shared__ __align__(16) float kt[64][52];     // 13.3KB
    __shared__ __align__(16) float vt[48][36];     // 6.75KB

    int bh = blockIdx.y, b = bh >> 4, h = bh & 15;
    int ibase = blockIdx.x * 16;
    int t = threadIdx.x, warp = t >> 5, lane = t & 31;
    int g = lane >> 2, l4 = lane & 3;

    // preload bias strip (scores rows contiguous) into p
    {
        const float4* src = (const float4*)(scores + (((size_t)bh * II) + ibase) * II);
        for (int e = t; e < 16 * 192; e += 256) {
            int r = e / 192, c4 = e % 192;
            *(float4*)&p[r][c4 * 4] = src[(size_t)r * 192 + c4];
        }
    }
    // stage q strip raw
    if (t < 192) {
        int r = t / 12, dq = t % 12;
        float4 vq = *(const float4*)&q[(((size_t)b * II + ibase + r) * HH + h) * DD + dq * 4];
        qraw[r][dq * 4 + 0] = vq.x; qraw[r][dq * 4 + 1] = vq.y;
        qraw[r][dq * 4 + 2] = vq.z; qraw[r][dq * 4 + 3] = vq.w;
    }
    __syncthreads();

    // per-warp register-resident q fragments (hi/lo), all 6 k-steps
    unsigned uah[6][4], ual[6][4];
    #pragma unroll
    for (int ks = 0; ks < 6; ks++) {
        int kk = ks * 8;
        float r0 = qraw[g][kk + l4];
        float r1 = qraw[g + 8][kk + l4];
        float r2 = qraw[g][kk + l4 + 4];
        float r3 = qraw[g + 8][kk + l4 + 4];
        uah[ks][0] = f2tf(r0); ual[ks][0] = f2tf(r0 - __uint_as_float(uah[ks][0]));
        uah[ks][1] = f2tf(r1); ual[ks][1] = f2tf(r1 - __uint_as_float(uah[ks][1]));
        uah[ks][2] = f2tf(r2); ual[ks][2] = f2tf(r2 - __uint_as_float(uah[ks][2]));
        uah[ks][3] = f2tf(r3); ual[ks][3] = f2tf(r3 - __uint_as_float(uah[ks][3]));
    }

    const float sc = rsqrtf(48.f);

    // qk: loop j-tiles of 64; warp w owns n-tile w (8 j-cols)
    for (int jt = 0; jt < II / 64; jt++) {
        __syncthreads();   // prev tile's mma reads done before restage
        {
            int j0 = jt * 64;
            for (int e = t; e < 768; e += 256) {
                int r = e / 12, dq = e % 12;
                float4 vk = *(const float4*)&k[(((size_t)b * II + j0 + r) * HH + h) * DD + dq * 4];
                kt[r][dq * 4 + 0] = vk.x; kt[r][dq * 4 + 1] = vk.y;
                kt[r][dq * 4 + 2] = vk.z; kt[r][dq * 4 + 3] = vk.w;
            }
        }
        __syncthreads();
        float acc[4] = {0.f, 0.f, 0.f, 0.f};
        int n = warp * 8 + g;
        #pragma unroll
        for (int ks = 0; ks < 6; ks++) {
            int kk = ks * 8;
            float rb0 = kt[n][kk + l4];
            float rb1 = kt[n][kk + l4 + 4];
            unsigned bh2[2], bl2[2];
            bh2[0] = f2tf(rb0); bl2[0] = f2tf(rb0 - __uint_as_float(bh2[0]));
            bh2[1] = f2tf(rb1); bl2[1] = f2tf(rb1 - __uint_as_float(bh2[1]));
            mma_tf32(acc, uah[ks], bh2);
            mma_tf32(acc, uah[ks], bl2);
            mma_tf32(acc, ual[ks], bh2);
        }
        // s = qk*sc + bias (bias already in p)
        int jc = jt * 64 + warp * 8 + 2 * l4;
        p[g][jc]     += acc[0] * sc;
        p[g][jc + 1] += acc[1] * sc;
        p[g + 8][jc]     += acc[2] * sc;
        p[g + 8][jc + 1] += acc[3] * sc;
    }
    __syncthreads();

    // softmax over j for 16 rows (8 warps, 2 rows each)
    for (int r = warp; r < 16; r += 8) {
        float mx = -1e30f;
        for (int j = lane; j < II; j += 32) mx = fmaxf(mx, p[r][j]);
        #pragma unroll
        for (int off = 16; off; off >>= 1) mx = fmaxf(mx, __shfl_xor_sync(0xffffffffu, mx, off));
        float sum = 0.f;
        for (int j = lane; j < II; j += 32) {
            float e = expf(p[r][j] - mx); p[r][j] = e; sum += e;
        }
        #pragma unroll
        for (int off = 16; off; off >>= 1) sum += __shfl_xor_sync(0xffffffffu, sum, off);
        float inv = 1.f / sum;
        for (int j = lane; j < II; j += 32) p[r][j] *= inv;
    }
    __syncthreads();

    // AV: o[i,d] = sum_j p[i][j] * v[j][d]   (192 active compute threads)
    int ia = t / 24, d0 = t % 24;
    float acc2[2][2] = {};
    for (int jt = 0; jt < II / 32; jt++) {
        for (int e = t; e < 32 * 48; e += 256) {
            int jj = e / 48, d = e % 48;
            vt[d][jj] = v[(((size_t)b * II + jt * 32 + jj) * HH + h) * DD + d];
        }
        __syncthreads();
        if (t < 192) {
            #pragma unroll
            for (int jj = 0; jj < 32; jj += 4) {
                float4 p0 = *(const float4*)&p[ia][jt * 32 + jj];
                float4 p1 = *(const float4*)&p[ia + 8][jt * 32 + jj];
                float4 v0 = *(const float4*)&vt[d0][jj];
                float4 v1 = *(const float4*)&vt[d0 + 24][jj];
                acc2[0][0] += p0.x*v0.x + p0.y*v0.y + p0.z*v0.z + p0.w*v0.w;
                acc2[0][1] += p0.x*v1.x + p0.y*v1.y + p0.z*v1.z + p0.w*v1.w;
                acc2[1][0] += p1.x*v0.x + p1.y*v0.y + p1.z*v0.z + p1.w*v0.w;
                acc2[1][1] += p1.x*v1.x + p1.y*v1.y + p1.z*v1.z + p1.w*v1.w;
            }
        }
        __syncthreads();
    }
    if (t < 192) {
        #pragma unroll
        for (int u = 0; u < 2; u++)
            #pragma unroll
            for (int w2 = 0; w2 < 2; w2++) {
                int i = ibase + ia + u * 8;
                int d = d0 + w2 * 24;
                size_t gi = (((size_t)b * II + i) * HH + h) * DD + d;
                float gt = 1.f / (1.f + expf(-gbuf[gi]));
                o[gi] = acc2[u][w2] * gt;
            }
    }
}

// ---------------- host launch ----------------
static float* sym(const void* s) {
    void* p = nullptr;
    cudaGetSymbolAddress(&p, s);
    return (float*)p;
}

extern "C" void kernel_launch(void* const* d_in, const int* in_sizes, int n_in,
                              void* d_out, int out_size)
{
    const float* a_i      = (const float*)d_in[0];
    const float* s_i      = (const float*)d_in[1];
    const float* z_ij     = (const float*)d_in[2];
    const float* beta_ij  = (const float*)d_in[3];
    const float* lns_w    = (const float*)d_in[4];
    const float* lns_b    = (const float*)d_in[5];
    const float* Ws       = (const float*)d_in[6];
    const float* bs       = (const float*)d_in[7];
    const float* Wnb      = (const float*)d_in[8];
    const float* Wq       = (const float*)d_in[9];
    const float* bq       = (const float*)d_in[10];
    const float* Wk       = (const float*)d_in[11];
    const float* Wv       = (const float*)d_in[12];
    const float* lnb_w    = (const float*)d_in[13];
    const float* lnb_b    = (const float*)d_in[14];
    const float* Wb       = (const float*)d_in[15];
    const float* Wg       = (const float*)d_in[16];
    const float* Wo       = (const float*)d_in[17];
    const float* Ws_out   = (const float*)d_in[18];
    const float* bs_out   = (const float*)d_in[19];
    float* out = (float*)d_out;

    float* p_aln  = sym(g_aln);
    float* p_sln  = sym(g_sln);
    float* p_t1   = sym(g_t1);
    float* p_t2   = sym(g_t2);
    float* p_a2   = sym(g_a2);
    float* p_q    = sym(g_q);
    float* p_k    = sym(g_k);
    float* p_v    = sym(g_v);
    float* p_g    = sym(g_gbuf);
    float* p_gate = sym(g_gate);
    float* p_sc   = sym(g_scores);
    float* p_o    = sym(g_o);

    const int NEL = ROWS * CA;

    // pair bias first (independent of everything else)
    {
        dim3 g(II / 64, ROWS);
        pairbias_tc_kernel<<<g, 256>>>(z_ij, beta_ij, lnb_w, lnb_b, Wb, p_sc);
    }

    // LayerNorms
    ln_kernel<<<ROWS, 256>>>(a_i, nullptr, nullptr, p_aln, CA);
    ln_kernel<<<ROWS, 256>>>(s_i, lns_w, lns_b, p_sln, CS);

    // AdaLN: t1 = sln@Ws + bs ; t2 = sln@Wnb
    {
        GemmBatch gb = {};
        gb.j[0] = { Ws,  bs,      nullptr, p_t1, 0 };
        gb.j[1] = { Wnb, nullptr, nullptr, p_t2, 0 };
        dim3 g(CA / 64, ROWS / 128, 2);
        gemm_tc_kernel<<<g, 256>>>(p_sln, gb, ROWS, CA, CS);
    }
    adaln_ew_kernel<<<(NEL + 255) / 256, 256>>>(p_t1, p_t2, p_aln, p_a2, NEL);

    // projections q,k,v,g
    {
        GemmBatch gb = {};
        gb.j[0] = { Wq, bq,      nullptr, p_q, 0 };
        gb.j[1] = { Wk, nullptr, nullptr, p_k, 0 };
        gb.j[2] = { Wv, nullptr, nullptr, p_v, 0 };
        gb.j[3] = { Wg, nullptr, nullptr, p_g, 0 };
        dim3 g(HC / 64, ROWS / 128, 4);
        gemm_tc_kernel<<<g, 256>>>(p_a2, gb, ROWS, HC, CA);
    }

    // output gate from raw s_i (sigmoid)
    {
        GemmBatch gb = {};
        gb.j[0] = { Ws_out, bs_out, nullptr, p_gate, 1 };
        dim3 g(CA / 64, ROWS / 128, 1);
        gemm_tc_kernel<<<g, 256>>>(s_i, gb, ROWS, CA, CS);
    }

    // fused attention: qk + bias + softmax + AV + gate
    {
        dim3 g(II / 16, BB * HH);
        attn_kernel<<<g, 256>>>(p_sc, p_q, p_k, p_v, p_g, p_o);
    }

    // out = gate * (o @ Wo)
    {
        GemmBatch gb = {};
        gb.j[0] = { Wo, nullptr, p_gate, out, 0 };
        dim3 g(CA / 64, ROWS / 128, 1);
        gemm_tc_kernel<<<g, 256>>>(p_o, gb, ROWS, CA, HC);
    }
}

// round 9
// speedup vs baseline: 1.1413x; 1.1413x over previous
#include <cuda_runtime.h>
#include <cuda_bf16.h>
#include <math.h>

// Problem constants
#define BB 2
#define II 768
#define CA 768
#define CS 384
#define CZ 128
#define HH 16
#define DD 48
#define HC 768
#define ROWS (BB*II)          // 1536
#define EPS 1e-5f

// ---------------- device scratch (no allocations allowed) ----------------
__device__ float g_aln  [ROWS*CA];
__device__ float g_sln  [ROWS*CS];
__device__ float g_t1   [ROWS*CA];
__device__ float g_t2   [ROWS*CA];
__device__ float g_a2   [ROWS*CA];
__device__ float g_q    [ROWS*HC];
__device__ float g_k    [ROWS*HC];
__device__ float g_v    [ROWS*HC];
__device__ float g_gbuf [ROWS*HC];
__device__ float g_gate [ROWS*CA];
__device__ float g_scores[(size_t)BB*HH*II*II];   // [b][h][i][j]  ~75.5 MB
__device__ float g_o    [ROWS*HC];

// ---------------- tf32 helpers ----------------
__device__ __forceinline__ unsigned f2tf(float x) {
    unsigned u;
    asm("cvt.rna.tf32.f32 %0, %1;" : "=r"(u) : "f"(x));
    return u;
}
__device__ __forceinline__ float tf32r(float x) {
    return __uint_as_float(f2tf(x));
}

__device__ __forceinline__ void mma_tf32(float* d, const unsigned* a, const unsigned* b) {
    asm volatile(
        "mma.sync.aligned.m16n8k8.row.col.f32.tf32.tf32.f32 "
        "{%0,%1,%2,%3}, {%4,%5,%6,%7}, {%8,%9}, {%0,%1,%2,%3};"
        : "+f"(d[0]), "+f"(d[1]), "+f"(d[2]), "+f"(d[3])
        : "r"(a[0]), "r"(a[1]), "r"(a[2]), "r"(a[3]), "r"(b[0]), "r"(b[1]));
}

// One 8-deep K slice for gemm_tc ([k][m] A layout, [k][n] B layout)
template<int SA, int SB>
__device__ __forceinline__ void do_mma8(const float* AhP, const float* AlP,
                                        const float* BhP, const float* BlP,
                                        int kk, int wm, int wn, int l4, int g,
                                        float acc[2][4][4])
{
    unsigned ah[2][4], al[2][4], bh[4][2], bl[4][2];
    const float* r0 = AhP + (kk + l4) * SA;
    const float* r1 = AhP + (kk + l4 + 4) * SA;
    const float* s0 = AlP + (kk + l4) * SA;
    const float* s1 = AlP + (kk + l4 + 4) * SA;
    #pragma unroll
    for (int mt = 0; mt < 2; mt++) {
        int mm = wm + mt * 16;
        ah[mt][0] = __float_as_uint(r0[mm + g]);
        ah[mt][1] = __float_as_uint(r0[mm + g + 8]);
        ah[mt][2] = __float_as_uint(r1[mm + g]);
        ah[mt][3] = __float_as_uint(r1[mm + g + 8]);
        al[mt][0] = __float_as_uint(s0[mm + g]);
        al[mt][1] = __float_as_uint(s0[mm + g + 8]);
        al[mt][2] = __float_as_uint(s1[mm + g]);
        al[mt][3] = __float_as_uint(s1[mm + g + 8]);
    }
    const float* t0 = BhP + (kk + l4) * SB;
    const float* t1 = BhP + (kk + l4 + 4) * SB;
    const float* u0 = BlP + (kk + l4) * SB;
    const float* u1 = BlP + (kk + l4 + 4) * SB;
    #pragma unroll
    for (int nt = 0; nt < 4; nt++) {
        int nn = wn + nt * 8 + g;
        bh[nt][0] = __float_as_uint(t0[nn]);
        bh[nt][1] = __float_as_uint(t1[nn]);
        bl[nt][0] = __float_as_uint(u0[nn]);
        bl[nt][1] = __float_as_uint(u1[nn]);
    }
    #pragma unroll
    for (int mt = 0; mt < 2; mt++)
        #pragma unroll
        for (int nt = 0; nt < 4; nt++) {
            mma_tf32(acc[mt][nt], ah[mt], bh[nt]);
            mma_tf32(acc[mt][nt], ah[mt], bl[nt]);
            mma_tf32(acc[mt][nt], al[mt], bh[nt]);
        }
}

// ---------------- LayerNorm over rows ----------------
__global__ void ln_kernel(const float* __restrict__ x,
                          const float* __restrict__ w,
                          const float* __restrict__ b,
                          float* __restrict__ y, int C)
{
    int row = blockIdx.x;
    const float* xr = x + (size_t)row * C;
    float s1 = 0.f, s2 = 0.f;
    for (int c = threadIdx.x; c < C; c += blockDim.x) {
        float v = xr[c]; s1 += v; s2 += v * v;
    }
    __shared__ float red[64];
    #pragma unroll
    for (int o = 16; o; o >>= 1) {
        s1 += __shfl_xor_sync(0xffffffffu, s1, o);
        s2 += __shfl_xor_sync(0xffffffffu, s2, o);
    }
    int wid = threadIdx.x >> 5, lid = threadIdx.x & 31;
    if (lid == 0) { red[wid] = s1; red[wid + 32] = s2; }
    __syncthreads();
    if (wid == 0) {
        s1 = (lid < (blockDim.x >> 5)) ? red[lid] : 0.f;
        s2 = (lid < (blockDim.x >> 5)) ? red[lid + 32] : 0.f;
        #pragma unroll
        for (int o = 16; o; o >>= 1) {
            s1 += __shfl_xor_sync(0xffffffffu, s1, o);
            s2 += __shfl_xor_sync(0xffffffffu, s2, o);
        }
        if (lid == 0) { red[0] = s1; red[1] = s2; }
    }
    __syncthreads();
    float mean = red[0] / C;
    float var  = red[1] / C - mean * mean;
    float rs   = rsqrtf(var + EPS);
    float* yr = y + (size_t)row * C;
    for (int c = threadIdx.x; c < C; c += blockDim.x) {
        float v = (xr[c] - mean) * rs;
        if (w) v = v * w[c] + b[c];
        yr[c] = v;
    }
}

// ---------------- tf32 tensor-core GEMM, batched over blockIdx.z ----------
struct GemmJob { const float* A; const float* W; const float* bias;
                 const float* mul; float* out; int sig; };
struct GemmBatch { GemmJob j[4]; };

// C = A[M,K] @ W[K,N]; tile 128x64, 256 threads (8 warps, 4x2), warp tile 32x32.
// Double-buffered smem, single __syncthreads per K-tile. Per-job A pointer.
__global__ void __launch_bounds__(256)
gemm_tc_kernel(GemmBatch batch, int M, int N, int K)
{
    __shared__ float Ah[2][16][136], Al[2][16][136];
    __shared__ float Bh[2][16][72],  Bl[2][16][72];

    GemmJob jb = batch.j[blockIdx.z];
    const float* __restrict__ A = jb.A;
    const float* __restrict__ W = jb.W;

    int t = threadIdx.x;
    int m0 = blockIdx.y * 128, n0 = blockIdx.x * 64;
    int w = t >> 5, lane = t & 31;
    int wm = (w >> 1) * 32, wn = (w & 1) * 32;
    int l4 = lane & 3, g = lane >> 2;

    int am = t >> 1, ak = (t & 1) * 8;
    int bk = t >> 4, bn = (t & 15) * 4;
    const float* Ap = A + (size_t)(m0 + am) * K + ak;
    const float* Wp = W + (size_t)bk * N + n0 + bn;

    float acc[2][4][4] = {};
    int nkt = K >> 4;

    float4 a0 = *(const float4*)Ap;
    float4 a1 = *(const float4*)(Ap + 4);
    float4 b0 = *(const float4*)Wp;

    for (int kt = 0; kt < nkt; kt++) {
        int p = kt & 1;
        {   // hi/lo split + store current tile into buffer p
            float av[8] = {a0.x,a0.y,a0.z,a0.w,a1.x,a1.y,a1.z,a1.w};
            #pragma unroll
            for (int u = 0; u < 8; u++) {
                float hi = tf32r(av[u]);
                Ah[p][ak + u][am] = hi;
                Al[p][ak + u][am] = tf32r(av[u] - hi);
            }
            float bv[4] = {b0.x, b0.y, b0.z, b0.w};
            float h0 = tf32r(bv[0]), h1 = tf32r(bv[1]);
            float h2 = tf32r(bv[2]), h3 = tf32r(bv[3]);
            *(float4*)&Bh[p][bk][bn] = make_float4(h0, h1, h2, h3);
            *(float4*)&Bl[p][bk][bn] = make_float4(tf32r(bv[0]-h0), tf32r(bv[1]-h1),
                                                   tf32r(bv[2]-h2), tf32r(bv[3]-h3));
        }
        __syncthreads();
        if (kt + 1 < nkt) {     // prefetch next tile (overlaps mma)
            const float* Ap2 = Ap + (size_t)(kt + 1) * 16;
            a0 = *(const float4*)Ap2;
            a1 = *(const float4*)(Ap2 + 4);
            b0 = *(const float4*)(Wp + (size_t)(kt + 1) * 16 * N);
        }
        do_mma8<136, 72>(&Ah[p][0][0], &Al[p][0][0], &Bh[p][0][0], &Bl[p][0][0], 0, wm, wn, l4, g, acc);
        do_mma8<136, 72>(&Ah[p][0][0], &Al[p][0][0], &Bh[p][0][0], &Bl[p][0][0], 8, wm, wn, l4, g, acc);
    }

    // epilogue
    const float* bias = jb.bias;
    const float* mul  = jb.mul;
    float* out = jb.out;
    int sig = jb.sig;
    #pragma unroll
    for (int mt = 0; mt < 2; mt++)
        #pragma unroll
        for (int nt = 0; nt < 4; nt++) {
            int n = n0 + wn + nt * 8 + l4 * 2;
            float bx = 0.f, by = 0.f;
            if (bias) { bx = bias[n]; by = bias[n + 1]; }
            #pragma unroll
            for (int half = 0; half < 2; half++) {
                int m = m0 + wm + mt * 16 + g + half * 8;
                float x = acc[mt][nt][half * 2]     + bx;
                float y = acc[mt][nt][half * 2 + 1] + by;
                if (sig) {
                    x = 1.f / (1.f + expf(-x));
                    y = 1.f / (1.f + expf(-y));
                }
                if (mul) {
                    float2 mv = *(const float2*)&mul[(size_t)m * N + n];
                    x *= mv.x; y *= mv.y;
                }
                *(float2*)&out[(size_t)m * N + n] = make_float2(x, y);
            }
        }
}

// ---------------- elementwise ----------------
__global__ void adaln_ew_kernel(const float* __restrict__ t1,
                                const float* __restrict__ t2,
                                const float* __restrict__ aln,
                                float* __restrict__ a2, int n)
{
    int i = blockIdx.x * blockDim.x + threadIdx.x;
    if (i < n) {
        float s = 1.f / (1.f + expf(-t1[i]));
        a2[i] = s * aln[i] + t2[i];
    }
}

// ---------------- pair bias (tensor core): scores = LN(z)@Wb + beta --------
// Block: 64 j-rows for fixed (b,i). 256 threads = 8 warps (4 m-tiles x 2 n-tiles).
__global__ void __launch_bounds__(256)
pairbias_tc_kernel(const float* __restrict__ z,
                   const float* __restrict__ beta,
                   const float* __restrict__ lnb_w,
                   const float* __restrict__ lnb_b,
                   const float* __restrict__ Wb,
                   float* __restrict__ scores)
{
    __shared__ __align__(16) float zt[64][132];    // raw z tile, row-major
    __shared__ float wbh[128][24], wbl[128][24];   // [c][h] hi/lo of lnb_w*Wb
    __shared__ float bt[64][17];                   // beta tile
    __shared__ float colsum[16], consth[16];
    __shared__ float mean_s[64], rs_s[64];
    __shared__ float ps1[64][4], ps2[64][4];

    int t  = threadIdx.x;
    int j0 = blockIdx.x * 64;
    int bi = blockIdx.y;
    int b  = bi / II, i = bi % II;

    // stage wb hi/lo
    for (int e = t; e < 128 * 16; e += 256) {
        int c = e >> 4, h = e & 15;
        float wv = lnb_w[c] * Wb[c * 16 + h];
        float hi = tf32r(wv);
        wbh[c][h] = hi;
        wbl[c][h] = tf32r(wv - hi);
    }
    // stage beta tile
    {
        const float4* bg = (const float4*)(beta + ((size_t)bi * II + j0) * HH);
        float4 v = bg[t];
        int j = t >> 2, h = (t & 3) * 4;
        bt[j][h + 0] = v.x; bt[j][h + 1] = v.y;
        bt[j][h + 2] = v.z; bt[j][h + 3] = v.w;
    }
    // stage z tile (raw)
    {
        const float4* zg = (const float4*)(z + ((size_t)bi * II + j0) * CZ);
        #pragma unroll
        for (int e = t; e < 2048; e += 256) {
            int r = e >> 5, q = e & 31;
            *(float4*)&zt[r][q * 4] = zg[(size_t)r * 32 + q];
        }
    }
    __syncthreads();

    // row-stat partials: 4 threads per row
    {
        int srow = t >> 2, seg = t & 3;
        const float* zr = zt[srow];
        float s1 = 0.f, s2 = 0.f;
        #pragma unroll
        for (int u = 0; u < 32; u++) {
            float v = zr[seg * 32 + u];
            s1 += v; s2 += v * v;
        }
        ps1[srow][seg] = s1; ps2[srow][seg] = s2;
    }
    if (t < 16) {
        float cs = 0.f, ch = 0.f;
        for (int c = 0; c < 128; c++) {
            cs += wbh[c][t] + wbl[c][t];
            ch += lnb_b[c] * Wb[c * 16 + t];
        }
        colsum[t] = cs; consth[t] = ch;
    }
    __syncthreads();
    if (t < 64) {
        float a  = ps1[t][0] + ps1[t][1] + ps1[t][2] + ps1[t][3];
        float b2 = ps2[t][0] + ps2[t][1] + ps2[t][2] + ps2[t][3];
        float m  = a * (1.f / 128.f);
        float var = b2 * (1.f / 128.f) - m * m;
        mean_s[t] = m;
        rs_s[t]   = rsqrtf(var + EPS);
    }

    // mma: dot[j][h] = z_row_j . wb2_col_h   (tf32 3x)
    int w = t >> 5, lane = t & 31, g = lane >> 2, l4 = lane & 3;
    int mb = (w >> 1) * 16, nb = (w & 1) * 8;
    float acc[4] = {0.f, 0.f, 0.f, 0.f};
    #pragma unroll
    for (int ks = 0; ks < 16; ks++) {
        int kk = ks * 8;
        float r0 = zt[mb + g][kk + l4];
        float r1 = zt[mb + g + 8][kk + l4];
        float r2 = zt[mb + g][kk + l4 + 4];
        float r3 = zt[mb + g + 8][kk + l4 + 4];
        unsigned ah[4], al[4];
        ah[0] = f2tf(r0); al[0] = f2tf(r0 - __uint_as_float(ah[0]));
        ah[1] = f2tf(r1); al[1] = f2tf(r1 - __uint_as_float(ah[1]));
        ah[2] = f2tf(r2); al[2] = f2tf(r2 - __uint_as_float(ah[2]));
        ah[3] = f2tf(r3); al[3] = f2tf(r3 - __uint_as_float(ah[3]));
        unsigned bh2[2], bl2[2];
        bh2[0] = __float_as_uint(wbh[kk + l4][nb + g]);
        bh2[1] = __float_as_uint(wbh[kk + l4 + 4][nb + g]);
        bl2[0] = __float_as_uint(wbl[kk + l4][nb + g]);
        bl2[1] = __float_as_uint(wbl[kk + l4 + 4][nb + g]);
        mma_tf32(acc, ah, bh2);
        mma_tf32(acc, ah, bl2);
        mma_tf32(acc, al, bh2);
    }
    __syncthreads();                 // zt reads done; alias as pacc
    float* pacc = &zt[0][0];         // [64][17]
    pacc[(mb + g)     * 17 + nb + 2 * l4]     = acc[0];
    pacc[(mb + g)     * 17 + nb + 2 * l4 + 1] = acc[1];
    pacc[(mb + g + 8) * 17 + nb + 2 * l4]     = acc[2];
    pacc[(mb + g + 8) * 17 + nb + 2 * l4 + 1] = acc[3];
    __syncthreads();

    // epilogue: LN closed form + beta; coalesced score writes
    {
        int j = t & 63, hb = t >> 6;
        float mean = mean_s[j], rs = rs_s[j];
        #pragma unroll
        for (int u = 0; u < 4; u++) {
            int h = hb * 4 + u;
            float v = pacc[j * 17 + h];
            v = rs * (v - mean * colsum[h]) + consth[h] + bt[j][h];
            scores[(((size_t)(b * 16 + h)) * II + i) * II + j0 + j] = v;
        }
    }
}

// ---------------- scores += q.k/sqrt(D), tf32 tensor-core ------------------
// Block: 128 threads (4 warps, 2x2), 64x64 tile, K=48 in two 24-wide phases.
__global__ void __launch_bounds__(128)
qk_tc_kernel(const float* __restrict__ q, const float* __restrict__ k,
             float* __restrict__ scores)
{
    __shared__ float Qh[24][72], Ql[24][72], Kh[24][72], Kl[24][72];
    int bh = blockIdx.z, b = bh >> 4, h = bh & 15;
    int i0 = blockIdx.y * 64, j0 = blockIdx.x * 64;
    int t = threadIdx.x, w = t >> 5, lane = t & 31;
    int wm = (w >> 1) * 32, wn = (w & 1) * 32;
    int l4 = lane & 3, g = lane >> 2;

    float acc[2][4][4] = {};

    #pragma unroll
    for (int ph = 0; ph < 2; ph++) {
        {
            int row = t & 63, which = t >> 6;
            const float* src = (which ? k : q)
                + (((size_t)b * II + (which ? j0 : i0) + row) * HH + h) * DD + ph * 24;
            float (*Sh)[72] = which ? Kh : Qh;
            float (*Sl)[72] = which ? Kl : Ql;
            #pragma unroll
            for (int u = 0; u < 24; u += 4) {
                float4 v = *(const float4*)(src + u);
                float vv[4] = {v.x, v.y, v.z, v.w};
                #pragma unroll
                for (int c = 0; c < 4; c++) {
                    float hi = tf32r(vv[c]);
                    Sh[u + c][row] = hi;
                    Sl[u + c][row] = tf32r(vv[c] - hi);
                }
            }
        }
        __syncthreads();
        do_mma8<72, 72>(&Qh[0][0], &Ql[0][0], &Kh[0][0], &Kl[0][0], 0,  wm, wn, l4, g, acc);
        do_mma8<72, 72>(&Qh[0][0], &Ql[0][0], &Kh[0][0], &Kl[0][0], 8,  wm, wn, l4, g, acc);
        do_mma8<72, 72>(&Qh[0][0], &Ql[0][0], &Kh[0][0], &Kl[0][0], 16, wm, wn, l4, g, acc);
        __syncthreads();
    }

    const float sc = rsqrtf(48.f);
    #pragma unroll
    for (int mt = 0; mt < 2; mt++)
        #pragma unroll
        for (int nt = 0; nt < 4; nt++)
            #pragma unroll
            for (int half = 0; half < 2; half++) {
                int i = i0 + wm + mt * 16 + g + half * 8;
                int jj = j0 + wn + nt * 8 + l4 * 2;
                size_t idx = ((size_t)bh * II + i) * II + jj;
                float2 old = *(float2*)&scores[idx];
                old.x += acc[mt][nt][half * 2]     * sc;
                old.y += acc[mt][nt][half * 2 + 1] * sc;
                *(float2*)&scores[idx] = old;
            }
}

// ---------------- softmax over j + AV + gate: o[b,i,h,d] ----------------
__global__ void __launch_bounds__(192)
softmax_av_kernel(const float* __restrict__ scores,
                  const float* __restrict__ v,
                  const float* __restrict__ gbuf,
                  float* __restrict__ o)
{
    __shared__ __align__(16) float p[16][II];    // 48KB
    __shared__ __align__(16) float vt[48][68];   // [d][j] transposed, 64-wide tiles
    int bh = blockIdx.y, b = bh >> 4, h = bh & 15;
    int ibase = blockIdx.x * 16;
    int t = threadIdx.x, warp = t >> 5, lane = t & 31;

    for (int r = warp; r < 16; r += 6) {
        const float* srow = &scores[(((size_t)bh * II) + ibase + r) * II];
        float mx = -1e30f;
        for (int j = lane; j < II; j += 32) {
            float s = srow[j]; p[r][j] = s; mx = fmaxf(mx, s);
        }
        #pragma unroll
        for (int off = 16; off; off >>= 1) mx = fmaxf(mx, __shfl_xor_sync(0xffffffffu, mx, off));
        float sum = 0.f;
        for (int j = lane; j < II; j += 32) {
            float e = expf(p[r][j] - mx); p[r][j] = e; sum += e;
        }
        #pragma unroll
        for (int off = 16; off; off >>= 1) sum += __shfl_xor_sync(0xffffffffu, sum, off);
        float inv = 1.f / sum;
        for (int j = lane; j < II; j += 32) p[r][j] *= inv;
    }
    __syncthreads();

    int ia = t / 24, d0 = t % 24;
    float acc[2][2] = {};
    for (int jt = 0; jt < II / 64; jt++) {
        for (int e = t; e < 64 * 48; e += 192) {
            int jj = e / 48, d = e % 48;
            vt[d][jj] = v[(((size_t)b * II + jt * 64 + jj) * HH + h) * DD + d];
        }
        __syncthreads();
        #pragma unroll
        for (int jj = 0; jj < 64; jj += 4) {
            float4 p0 = *(const float4*)&p[ia][jt * 64 + jj];
            float4 p1 = *(const float4*)&p[ia + 8][jt * 64 + jj];
            float4 v0 = *(const float4*)&vt[d0][jj];
            float4 v1 = *(const float4*)&vt[d0 + 24][jj];
            acc[0][0] += p0.x*v0.x + p0.y*v0.y + p0.z*v0.z + p0.w*v0.w;
            acc[0][1] += p0.x*v1.x + p0.y*v1.y + p0.z*v1.z + p0.w*v1.w;
            acc[1][0] += p1.x*v0.x + p1.y*v0.y + p1.z*v0.z + p1.w*v0.w;
            acc[1][1] += p1.x*v1.x + p1.y*v1.y + p1.z*v1.z + p1.w*v1.w;
        }
        __syncthreads();
    }
    #pragma unroll
    for (int u = 0; u < 2; u++)
        #pragma unroll
        for (int w2 = 0; w2 < 2; w2++) {
            int i = ibase + ia + u * 8;
            int d = d0 + w2 * 24;
            size_t gi = (((size_t)b * II + i) * HH + h) * DD + d;
            float g = 1.f / (1.f + expf(-gbuf[gi]));
            o[gi] = acc[u][w2] * g;
        }
}

// ---------------- host launch ----------------
static float* sym(const void* s) {
    void* p = nullptr;
    cudaGetSymbolAddress(&p, s);
    return (float*)p;
}

extern "C" void kernel_launch(void* const* d_in, const int* in_sizes, int n_in,
                              void* d_out, int out_size)
{
    const float* a_i      = (const float*)d_in[0];
    const float* s_i      = (const float*)d_in[1];
    const float* z_ij     = (const float*)d_in[2];
    const float* beta_ij  = (const float*)d_in[3];
    const float* lns_w    = (const float*)d_in[4];
    const float* lns_b    = (const float*)d_in[5];
    const float* Ws       = (const float*)d_in[6];
    const float* bs       = (const float*)d_in[7];
    const float* Wnb      = (const float*)d_in[8];
    const float* Wq       = (const float*)d_in[9];
    const float* bq       = (const float*)d_in[10];
    const float* Wk       = (const float*)d_in[11];
    const float* Wv       = (const float*)d_in[12];
    const float* lnb_w    = (const float*)d_in[13];
    const float* lnb_b    = (const float*)d_in[14];
    const float* Wb       = (const float*)d_in[15];
    const float* Wg       = (const float*)d_in[16];
    const float* Wo       = (const float*)d_in[17];
    const float* Ws_out   = (const float*)d_in[18];
    const float* bs_out   = (const float*)d_in[19];
    float* out = (float*)d_out;

    float* p_aln  = sym(g_aln);
    float* p_sln  = sym(g_sln);
    float* p_t1   = sym(g_t1);
    float* p_t2   = sym(g_t2);
    float* p_a2   = sym(g_a2);
    float* p_q    = sym(g_q);
    float* p_k    = sym(g_k);
    float* p_v    = sym(g_v);
    float* p_g    = sym(g_gbuf);
    float* p_gate = sym(g_gate);
    float* p_sc   = sym(g_scores);
    float* p_o    = sym(g_o);

    const int NEL = ROWS * CA;

    // pair bias first (independent of everything else)
    {
        dim3 g(II / 64, ROWS);
        pairbias_tc_kernel<<<g, 256>>>(z_ij, beta_ij, lnb_w, lnb_b, Wb, p_sc);
    }

    // LayerNorms
    ln_kernel<<<ROWS, 256>>>(a_i, nullptr, nullptr, p_aln, CA);
    ln_kernel<<<ROWS, 256>>>(s_i, lns_w, lns_b, p_sln, CS);

    // AdaLN pair + output gate, all K=384, one batched launch
    {
        GemmBatch gb = {};
        gb.j[0] = { p_sln, Ws,     bs,      nullptr, p_t1,   0 };
        gb.j[1] = { p_sln, Wnb,    nullptr, nullptr, p_t2,   0 };
        gb.j[2] = { s_i,   Ws_out, bs_out,  nullptr, p_gate, 1 };
        dim3 g(CA / 64, ROWS / 128, 3);
        gemm_tc_kernel<<<g, 256>>>(gb, ROWS, CA, CS);
    }
    adaln_ew_kernel<<<(NEL + 255) / 256, 256>>>(p_t1, p_t2, p_aln, p_a2, NEL);

    // projections q,k,v,g (K=768)
    {
        GemmBatch gb = {};
        gb.j[0] = { p_a2, Wq, bq,      nullptr, p_q, 0 };
        gb.j[1] = { p_a2, Wk, nullptr, nullptr, p_k, 0 };
        gb.j[2] = { p_a2, Wv, nullptr, nullptr, p_v, 0 };
        gb.j[3] = { p_a2, Wg, nullptr, nullptr, p_g, 0 };
        dim3 g(HC / 64, ROWS / 128, 4);
        gemm_tc_kernel<<<g, 256>>>(gb, ROWS, HC, CA);
    }

    // scores += qk/sqrt(D)
    {
        dim3 g(II / 64, II / 64, BB * HH);
        qk_tc_kernel<<<g, 128>>>(p_q, p_k, p_sc);
    }

    // softmax + AV + gate
    {
        dim3 g(II / 16, BB * HH);
        softmax_av_kernel<<<g, 192>>>(p_sc, p_v, p_g, p_o);
    }

    // out = gate * (o @ Wo)
    {
        GemmBatch gb = {};
        gb.j[0] = { p_o, Wo, nullptr, p_gate, out, 0 };
        dim3 g(CA / 64, ROWS / 128, 1);
        gemm_tc_kernel<<<g, 256>>>(gb, ROWS, CA, HC);
    }
}

// round 11
// speedup vs baseline: 1.1467x; 1.0047x over previous
#include <cuda_runtime.h>
#include <cuda_bf16.h>
#include <math.h>

// Problem constants
#define BB 2
#define II 768
#define CA 768
#define CS 384
#define CZ 128
#define HH 16
#define DD 48
#define HC 768
#define ROWS (BB*II)          // 1536
#define EPS 1e-5f

// ---------------- device scratch (no allocations allowed) ----------------
__device__ float g_aln  [ROWS*CA];
__device__ float g_sln  [ROWS*CS];
__device__ float g_t1   [ROWS*CA];
__device__ float g_t2   [ROWS*CA];
__device__ float g_a2   [ROWS*CA];
__device__ float g_q    [ROWS*HC];
__device__ float g_k    [ROWS*HC];
__device__ float g_v    [ROWS*HC];
__device__ float g_gbuf [ROWS*HC];
__device__ float g_gate [ROWS*CA];
__device__ float g_scores[(size_t)BB*HH*II*II];   // [b][h][i][j]  ~75.5 MB
__device__ float g_o    [ROWS*HC];

// ---------------- tf32 helpers ----------------
__device__ __forceinline__ unsigned f2tf(float x) {
    unsigned u;
    asm("cvt.rna.tf32.f32 %0, %1;" : "=r"(u) : "f"(x));
    return u;
}
__device__ __forceinline__ float tf32r(float x) {
    return __uint_as_float(f2tf(x));
}

__device__ __forceinline__ void mma_tf32(float* d, const unsigned* a, const unsigned* b) {
    asm volatile(
        "mma.sync.aligned.m16n8k8.row.col.f32.tf32.tf32.f32 "
        "{%0,%1,%2,%3}, {%4,%5,%6,%7}, {%8,%9}, {%0,%1,%2,%3};"
        : "+f"(d[0]), "+f"(d[1]), "+f"(d[2]), "+f"(d[3])
        : "r"(a[0]), "r"(a[1]), "r"(a[2]), "r"(a[3]), "r"(b[0]), "r"(b[1]));
}

// One 8-deep K slice for gemm_tc ([k][m] A layout, [k][n] B layout)
template<int SA, int SB>
__device__ __forceinline__ void do_mma8(const float* AhP, const float* AlP,
                                        const float* BhP, const float* BlP,
                                        int kk, int wm, int wn, int l4, int g,
                                        float acc[2][4][4])
{
    unsigned ah[2][4], al[2][4], bh[4][2], bl[4][2];
    const float* r0 = AhP + (kk + l4) * SA;
    const float* r1 = AhP + (kk + l4 + 4) * SA;
    const float* s0 = AlP + (kk + l4) * SA;
    const float* s1 = AlP + (kk + l4 + 4) * SA;
    #pragma unroll
    for (int mt = 0; mt < 2; mt++) {
        int mm = wm + mt * 16;
        ah[mt][0] = __float_as_uint(r0[mm + g]);
        ah[mt][1] = __float_as_uint(r0[mm + g + 8]);
        ah[mt][2] = __float_as_uint(r1[mm + g]);
        ah[mt][3] = __float_as_uint(r1[mm + g + 8]);
        al[mt][0] = __float_as_uint(s0[mm + g]);
        al[mt][1] = __float_as_uint(s0[mm + g + 8]);
        al[mt][2] = __float_as_uint(s1[mm + g]);
        al[mt][3] = __float_as_uint(s1[mm + g + 8]);
    }
    const float* t0 = BhP + (kk + l4) * SB;
    const float* t1 = BhP + (kk + l4 + 4) * SB;
    const float* u0 = BlP + (kk + l4) * SB;
    const float* u1 = BlP + (kk + l4 + 4) * SB;
    #pragma unroll
    for (int nt = 0; nt < 4; nt++) {
        int nn = wn + nt * 8 + g;
        bh[nt][0] = __float_as_uint(t0[nn]);
        bh[nt][1] = __float_as_uint(t1[nn]);
        bl[nt][0] = __float_as_uint(u0[nn]);
        bl[nt][1] = __float_as_uint(u1[nn]);
    }
    #pragma unroll
    for (int mt = 0; mt < 2; mt++)
        #pragma unroll
        for (int nt = 0; nt < 4; nt++) {
            mma_tf32(acc[mt][nt], ah[mt], bh[nt]);
            mma_tf32(acc[mt][nt], ah[mt], bl[nt]);
            mma_tf32(acc[mt][nt], al[mt], bh[nt]);
        }
}

// ---------------- LayerNorm over rows ----------------
__global__ void ln_kernel(const float* __restrict__ x,
                          const float* __restrict__ w,
                          const float* __restrict__ b,
                          float* __restrict__ y, int C)
{
    int row = blockIdx.x;
    const float* xr = x + (size_t)row * C;
    float s1 = 0.f, s2 = 0.f;
    for (int c = threadIdx.x; c < C; c += blockDim.x) {
        float v = xr[c]; s1 += v; s2 += v * v;
    }
    __shared__ float red[64];
    #pragma unroll
    for (int o = 16; o; o >>= 1) {
        s1 += __shfl_xor_sync(0xffffffffu, s1, o);
        s2 += __shfl_xor_sync(0xffffffffu, s2, o);
    }
    int wid = threadIdx.x >> 5, lid = threadIdx.x & 31;
    if (lid == 0) { red[wid] = s1; red[wid + 32] = s2; }
    __syncthreads();
    if (wid == 0) {
        s1 = (lid < (blockDim.x >> 5)) ? red[lid] : 0.f;
        s2 = (lid < (blockDim.x >> 5)) ? red[lid + 32] : 0.f;
        #pragma unroll
        for (int o = 16; o; o >>= 1) {
            s1 += __shfl_xor_sync(0xffffffffu, s1, o);
            s2 += __shfl_xor_sync(0xffffffffu, s2, o);
        }
        if (lid == 0) { red[0] = s1; red[1] = s2; }
    }
    __syncthreads();
    float mean = red[0] / C;
    float var  = red[1] / C - mean * mean;
    float rs   = rsqrtf(var + EPS);
    float* yr = y + (size_t)row * C;
    for (int c = threadIdx.x; c < C; c += blockDim.x) {
        float v = (xr[c] - mean) * rs;
        if (w) v = v * w[c] + b[c];
        yr[c] = v;
    }
}

// ---------------- tf32 tensor-core GEMM, batched over blockIdx.z ----------
struct GemmJob { const float* A; const float* W; const float* bias;
                 const float* mul; float* out; int sig; };
struct GemmBatch { GemmJob j[4]; };

// C = A[M,K] @ W[K,N]; tile 128x64, 256 threads (8 warps, 4x2), warp tile 32x32.
// Double-buffered smem, single __syncthreads per K-tile. Per-job A pointer.
__global__ void __launch_bounds__(256)
gemm_tc_kernel(GemmBatch batch, int M, int N, int K)
{
    __shared__ float Ah[2][16][136], Al[2][16][136];
    __shared__ float Bh[2][16][72],  Bl[2][16][72];

    GemmJob jb = batch.j[blockIdx.z];
    const float* __restrict__ A = jb.A;
    const float* __restrict__ W = jb.W;

    int t = threadIdx.x;
    int m0 = blockIdx.y * 128, n0 = blockIdx.x * 64;
    int w = t >> 5, lane = t & 31;
    int wm = (w >> 1) * 32, wn = (w & 1) * 32;
    int l4 = lane & 3, g = lane >> 2;

    int am = t >> 1, ak = (t & 1) * 8;
    int bk = t >> 4, bn = (t & 15) * 4;
    const float* Ap = A + (size_t)(m0 + am) * K + ak;
    const float* Wp = W + (size_t)bk * N + n0 + bn;

    float acc[2][4][4] = {};
    int nkt = K >> 4;

    float4 a0 = *(const float4*)Ap;
    float4 a1 = *(const float4*)(Ap + 4);
    float4 b0 = *(const float4*)Wp;

    for (int kt = 0; kt < nkt; kt++) {
        int p = kt & 1;
        {   // hi/lo split + store current tile into buffer p
            float av[8] = {a0.x,a0.y,a0.z,a0.w,a1.x,a1.y,a1.z,a1.w};
            #pragma unroll
            for (int u = 0; u < 8; u++) {
                float hi = tf32r(av[u]);
                Ah[p][ak + u][am] = hi;
                Al[p][ak + u][am] = tf32r(av[u] - hi);
            }
            float bv[4] = {b0.x, b0.y, b0.z, b0.w};
            float h0 = tf32r(bv[0]), h1 = tf32r(bv[1]);
            float h2 = tf32r(bv[2]), h3 = tf32r(bv[3]);
            *(float4*)&Bh[p][bk][bn] = make_float4(h0, h1, h2, h3);
            *(float4*)&Bl[p][bk][bn] = make_float4(tf32r(bv[0]-h0), tf32r(bv[1]-h1),
                                                   tf32r(bv[2]-h2), tf32r(bv[3]-h3));
        }
        __syncthreads();
        if (kt + 1 < nkt) {     // prefetch next tile (overlaps mma)
            const float* Ap2 = Ap + (size_t)(kt + 1) * 16;
            a0 = *(const float4*)Ap2;
            a1 = *(const float4*)(Ap2 + 4);
            b0 = *(const float4*)(Wp + (size_t)(kt + 1) * 16 * N);
        }
        do_mma8<136, 72>(&Ah[p][0][0], &Al[p][0][0], &Bh[p][0][0], &Bl[p][0][0], 0, wm, wn, l4, g, acc);
        do_mma8<136, 72>(&Ah[p][0][0], &Al[p][0][0], &Bh[p][0][0], &Bl[p][0][0], 8, wm, wn, l4, g, acc);
    }

    // epilogue
    const float* bias = jb.bias;
    const float* mul  = jb.mul;
    float* out = jb.out;
    int sig = jb.sig;
    #pragma unroll
    for (int mt = 0; mt < 2; mt++)
        #pragma unroll
        for (int nt = 0; nt < 4; nt++) {
            int n = n0 + wn + nt * 8 + l4 * 2;
            float bx = 0.f, by = 0.f;
            if (bias) { bx = bias[n]; by = bias[n + 1]; }
            #pragma unroll
            for (int half = 0; half < 2; half++) {
                int m = m0 + wm + mt * 16 + g + half * 8;
                float x = acc[mt][nt][half * 2]     + bx;
                float y = acc[mt][nt][half * 2 + 1] + by;
                if (sig) {
                    x = 1.f / (1.f + __expf(-x));
                    y = 1.f / (1.f + __expf(-y));
                }
                if (mul) {
                    float2 mv = *(const float2*)&mul[(size_t)m * N + n];
                    x *= mv.x; y *= mv.y;
                }
                *(float2*)&out[(size_t)m * N + n] = make_float2(x, y);
            }
        }
}

// ---------------- elementwise ----------------
__global__ void adaln_ew_kernel(const float* __restrict__ t1,
                                const float* __restrict__ t2,
                                const float* __restrict__ aln,
                                float* __restrict__ a2, int n)
{
    int i = blockIdx.x * blockDim.x + threadIdx.x;
    if (i < n) {
        float s = 1.f / (1.f + __expf(-t1[i]));
        a2[i] = s * aln[i] + t2[i];
    }
}

// ---------------- pair bias (scalar, proven): scores = LN(z)@Wb + beta ----
// Block: 64 j-rows for a fixed (b,i). 256 threads. No shuffles in hot loop.
__global__ void __launch_bounds__(256)
pairbias_kernel(const float* __restrict__ z,
                const float* __restrict__ beta,
                const float* __restrict__ lnb_w,
                const float* __restrict__ lnb_b,
                const float* __restrict__ Wb,
                float* __restrict__ scores)
{
    __shared__ __align__(16) float4 zt4[64][33];   // 64 rows x 128 c (pad 132 floats)
    __shared__ __align__(16) float  wb2[128][16];  // lnb_w[c]*Wb[c][h]
    __shared__ float  bt[64*16];                   // beta tile, xor-swizzled
    __shared__ float  colsum[16], consth[16];
    __shared__ float  mean_s[64], rs_s[64];
    __shared__ float  ps1[64][4], ps2[64][4];

    int t  = threadIdx.x;
    int j0 = blockIdx.x * 64;
    int bi = blockIdx.y;
    int b  = bi / II, i = bi % II;

    // stage wb2 (coalesced over Wb)
    for (int e = t; e < 128 * 16; e += 256) {
        int c = e >> 4, h = e & 15;
        wb2[c][h] = lnb_w[c] * Wb[c * 16 + h];
    }
    // stage beta tile: contiguous 4KB, xor-swizzled store for conflict-free read
    {
        const float4* bg = (const float4*)(beta + ((size_t)bi * II + j0) * HH);
        float4 v = bg[t];
        int e = t * 4;
        int j = e >> 4, h = e & 15;
        bt[j*16 + ((h+0 + j) & 15)] = v.x;
        bt[j*16 + ((h+1 + j) & 15)] = v.y;
        bt[j*16 + ((h+2 + j) & 15)] = v.z;
        bt[j*16 + ((h+3 + j) & 15)] = v.w;
    }
    // stage z tile: 64 rows x 128 c, fully contiguous 32KB
    {
        const float4* zg = (const float4*)(z + ((size_t)bi * II + j0) * CZ);
        #pragma unroll
        for (int e = t; e < 2048; e += 256) {
            int r = e >> 5, q = e & 31;
            zt4[r][q] = zg[(size_t)r * 32 + q];
        }
    }
    __syncthreads();

    // row stats partials: 4 threads per row
    {
        int srow = t >> 2, seg = t & 3;
        const float* zr = (const float*)zt4[srow];
        float s1 = 0.f, s2 = 0.f;
        #pragma unroll
        for (int u = 0; u < 32; u++) {
            float v = zr[seg * 32 + u];
            s1 += v; s2 += v * v;
        }
        ps1[srow][seg] = s1; ps2[srow][seg] = s2;
    }
    if (t < 16) {
        float cs = 0.f, ch = 0.f;
        for (int c = 0; c < 128; c++) {
            cs += wb2[c][t];
            ch += lnb_b[c] * Wb[c * 16 + t];
        }
        colsum[t] = cs; consth[t] = ch;
    }
    __syncthreads();
    if (t < 64) {
        float a  = ps1[t][0] + ps1[t][1] + ps1[t][2] + ps1[t][3];
        float b2 = ps2[t][0] + ps2[t][1] + ps2[t][2] + ps2[t][3];
        float m  = a * (1.f / 128.f);
        float var = b2 * (1.f / 128.f) - m * m;
        mean_s[t] = m;
        rs_s[t]   = rsqrtf(var + EPS);
    }

    // main: each thread owns one row, one 32-c split, all 16 heads
    int crow = t & 63, part = t >> 6;
    float acc[16] = {};
    {
        const float4* zr = zt4[crow];
        #pragma unroll
        for (int cc = 0; cc < 8; cc++) {
            int c4 = part * 8 + cc;
            float4 z4 = zr[c4];
            #pragma unroll
            for (int u = 0; u < 4; u++) {
                float zc = (u == 0) ? z4.x : (u == 1) ? z4.y : (u == 2) ? z4.z : z4.w;
                const float4* wr = (const float4*)wb2[c4 * 4 + u];
                #pragma unroll
                for (int hq = 0; hq < 4; hq++) {
                    float4 w = wr[hq];
                    acc[hq*4+0] += zc * w.x;
                    acc[hq*4+1] += zc * w.y;
                    acc[hq*4+2] += zc * w.z;
                    acc[hq*4+3] += zc * w.w;
                }
            }
        }
    }
    __syncthreads();                    // all zt reads done; alias zt as pacc
    float* pacc = (float*)zt4;          // [4][64][17]
    {
        int base = (part * 64 + crow) * 17;
        #pragma unroll
        for (int h = 0; h < 16; h++) pacc[base + h] = acc[h];
    }
    __syncthreads();

    // epilogue: combine splits, apply LN closed form + beta, write scores
    {
        int j = t & 63, hb = t >> 6;
        float mean = mean_s[j], rs = rs_s[j];
        #pragma unroll
        for (int u = 0; u < 4; u++) {
            int h = hb * 4 + u;
            float v = pacc[(0*64 + j)*17 + h] + pacc[(1*64 + j)*17 + h]
                    + pacc[(2*64 + j)*17 + h] + pacc[(3*64 + j)*17 + h];
            v = rs * (v - mean * colsum[h]) + consth[h] + bt[j*16 + ((h + j) & 15)];
            scores[(((size_t)(b*16 + h)) * II + i) * II + j0 + j] = v;
        }
    }
}

// ---------------- scores += q.k/sqrt(D), tf32 tensor-core ------------------
// Block: 128 threads (4 warps, 2x2), 64x64 tile, K=48 in two 24-wide phases.
__global__ void __launch_bounds__(128)
qk_tc_kernel(const float* __restrict__ q, const float* __restrict__ k,
             float* __restrict__ scores)
{
    __shared__ float Qh[24][72], Ql[24][72], Kh[24][72], Kl[24][72];
    int bh = blockIdx.z, b = bh >> 4, h = bh & 15;
    int i0 = blockIdx.y * 64, j0 = blockIdx.x * 64;
    int t = threadIdx.x, w = t >> 5, lane = t & 31;
    int wm = (w >> 1) * 32, wn = (w & 1) * 32;
    int l4 = lane & 3, g = lane >> 2;

    float acc[2][4][4] = {};

    #pragma unroll
    for (int ph = 0; ph < 2; ph++) {
        {
            int row = t & 63, which = t >> 6;
            const float* src = (which ? k : q)
                + (((size_t)b * II + (which ? j0 : i0) + row) * HH + h) * DD + ph * 24;
            float (*Sh)[72] = which ? Kh : Qh;
            float (*Sl)[72] = which ? Kl : Ql;
            #pragma unroll
            for (int u = 0; u < 24; u += 4) {
                float4 v = *(const float4*)(src + u);
                float vv[4] = {v.x, v.y, v.z, v.w};
                #pragma unroll
                for (int c = 0; c < 4; c++) {
                    float hi = tf32r(vv[c]);
                    Sh[u + c][row] = hi;
                    Sl[u + c][row] = tf32r(vv[c] - hi);
                }
            }
        }
        __syncthreads();
        do_mma8<72, 72>(&Qh[0][0], &Ql[0][0], &Kh[0][0], &Kl[0][0], 0,  wm, wn, l4, g, acc);
        do_mma8<72, 72>(&Qh[0][0], &Ql[0][0], &Kh[0][0], &Kl[0][0], 8,  wm, wn, l4, g, acc);
        do_mma8<72, 72>(&Qh[0][0], &Ql[0][0], &Kh[0][0], &Kl[0][0], 16, wm, wn, l4, g, acc);
        __syncthreads();
    }

    const float sc = rsqrtf(48.f);
    #pragma unroll
    for (int mt = 0; mt < 2; mt++)
        #pragma unroll
        for (int nt = 0; nt < 4; nt++)
            #pragma unroll
            for (int half = 0; half < 2; half++) {
                int i = i0 + wm + mt * 16 + g + half * 8;
                int jj = j0 + wn + nt * 8 + l4 * 2;
                size_t idx = ((size_t)bh * II + i) * II + jj;
                float2 old = *(float2*)&scores[idx];
                old.x += acc[mt][nt][half * 2]     * sc;
                old.y += acc[mt][nt][half * 2 + 1] * sc;
                *(float2*)&scores[idx] = old;
            }
}

// ---------------- softmax + AV (tensor core) + gate: o[b,i,h,d] -----------
// grid: (II/16, B*H). 192 threads = 6 warps; warp w owns d-tile w (8 d's).
__global__ void __launch_bounds__(192)
softmax_av_tc_kernel(const float* __restrict__ scores,
                     const float* __restrict__ v,
                     const float* __restrict__ gbuf,
                     float* __restrict__ o)
{
    __shared__ __align__(16) float p[16][772];     // exp values (unnormalized)
    __shared__ __align__(16) float ph[16][68], pl[16][68];
    __shared__ __align__(16) float vth[48][68], vtl[48][68];
    __shared__ float inv_s[16];

    int bh = blockIdx.y, b = bh >> 4, h = bh & 15;
    int ibase = blockIdx.x * 16;
    int t = threadIdx.x, warp = t >> 5, lane = t & 31;
    int g = lane >> 2, l4 = lane & 3;

    // phase 1: row max + exp (unnormalized); 6 warps cover 16 rows
    for (int r = warp; r < 16; r += 6) {
        const float* srow = &scores[(((size_t)bh * II) + ibase + r) * II];
        float mx = -1e30f;
        for (int j = lane; j < II; j += 32) {
            float s = srow[j]; p[r][j] = s; mx = fmaxf(mx, s);
        }
        #pragma unroll
        for (int off = 16; off; off >>= 1) mx = fmaxf(mx, __shfl_xor_sync(0xffffffffu, mx, off));
        float sum = 0.f;
        for (int j = lane; j < II; j += 32) {
            float e = __expf(p[r][j] - mx); p[r][j] = e; sum += e;
        }
        #pragma unroll
        for (int off = 16; off; off >>= 1) sum += __shfl_xor_sync(0xffffffffu, sum, off);
        if (lane == 0) inv_s[r] = 1.f / sum;
    }
    __syncthreads();

    // phase 2: AV via m16n8k8 tf32-3x. 12 chunks of 64 j.
    float acc[4] = {0.f, 0.f, 0.f, 0.f};
    int nn = warp * 8 + g;                  // this warp's d-row for B frags
    for (int jt = 0; jt < II / 64; jt++) {
        // stage p chunk hi/lo
        for (int e = t; e < 1024; e += 192) {
            int r = e >> 6, c = e & 63;
            float x = p[r][jt * 64 + c];
            float hi = tf32r(x);
            ph[r][c] = hi; pl[r][c] = tf32r(x - hi);
        }
        // stage v chunk hi/lo, transposed [d][j]
        for (int e = t; e < 3072; e += 192) {
            int jj = e / 48, d = e % 48;
            float x = v[(((size_t)b * II + jt * 64 + jj) * HH + h) * DD + d];
            float hi = tf32r(x);
            vth[d][jj] = hi; vtl[d][jj] = tf32r(x - hi);
        }
        __syncthreads();
        #pragma unroll
        for (int ks = 0; ks < 8; ks++) {
            int kk = ks * 8;
            unsigned ah[4], al[4], bh2[2], bl2[2];
            ah[0] = __float_as_uint(ph[g][kk + l4]);
            ah[1] = __float_as_uint(ph[g + 8][kk + l4]);
            ah[2] = __float_as_uint(ph[g][kk + l4 + 4]);
            ah[3] = __float_as_uint(ph[g + 8][kk + l4 + 4]);
            al[0] = __float_as_uint(pl[g][kk + l4]);
            al[1] = __float_as_uint(pl[g + 8][kk + l4]);
            al[2] = __float_as_uint(pl[g][kk + l4 + 4]);
            al[3] = __float_as_uint(pl[g + 8][kk + l4 + 4]);
            bh2[0] = __float_as_uint(vth[nn][kk + l4]);
            bh2[1] = __float_as_uint(vth[nn][kk + l4 + 4]);
            bl2[0] = __float_as_uint(vtl[nn][kk + l4]);
            bl2[1] = __float_as_uint(vtl[nn][kk + l4 + 4]);
            mma_tf32(acc, ah, bh2);
            mma_tf32(acc, ah, bl2);
            mma_tf32(acc, al, bh2);
        }
        __syncthreads();
    }

    // epilogue: normalize (deferred 1/sum), gate, write
    {
        int d = warp * 8 + 2 * l4;
        #pragma unroll
        for (int half = 0; half < 2; half++) {
            int r = g + half * 8;
            int i = ibase + r;
            float iv = inv_s[r];
            size_t gi = (((size_t)b * II + i) * HH + h) * DD + d;
            float2 gb2 = *(const float2*)&gbuf[gi];
            float g0 = 1.f / (1.f + __expf(-gb2.x));
            float g1 = 1.f / (1.f + __expf(-gb2.y));
            float2 r2;
            r2.x = acc[half * 2]     * iv * g0;
            r2.y = acc[half * 2 + 1] * iv * g1;
            *(float2*)&o[gi] = r2;
        }
    }
}

// ---------------- host launch ----------------
static float* sym(const void* s) {
    void* p = nullptr;
    cudaGetSymbolAddress(&p, s);
    return (float*)p;
}

extern "C" void kernel_launch(void* const* d_in, const int* in_sizes, int n_in,
                              void* d_out, int out_size)
{
    const float* a_i      = (const float*)d_in[0];
    const float* s_i      = (const float*)d_in[1];
    const float* z_ij     = (const float*)d_in[2];
    const float* beta_ij  = (const float*)d_in[3];
    const float* lns_w    = (const float*)d_in[4];
    const float* lns_b    = (const float*)d_in[5];
    const float* Ws       = (const float*)d_in[6];
    const float* bs       = (const float*)d_in[7];
    const float* Wnb      = (const float*)d_in[8];
    const float* Wq       = (const float*)d_in[9];
    const float* bq       = (const float*)d_in[10];
    const float* Wk       = (const float*)d_in[11];
    const float* Wv       = (const float*)d_in[12];
    const float* lnb_w    = (const float*)d_in[13];
    const float* lnb_b    = (const float*)d_in[14];
    const float* Wb       = (const float*)d_in[15];
    const float* Wg       = (const float*)d_in[16];
    const float* Wo       = (const float*)d_in[17];
    const float* Ws_out   = (const float*)d_in[18];
    const float* bs_out   = (const float*)d_in[19];
    float* out = (float*)d_out;

    float* p_aln  = sym(g_aln);
    float* p_sln  = sym(g_sln);
    float* p_t1   = sym(g_t1);
    float* p_t2   = sym(g_t2);
    float* p_a2   = sym(g_a2);
    float* p_q    = sym(g_q);
    float* p_k    = sym(g_k);
    float* p_v    = sym(g_v);
    float* p_g    = sym(g_gbuf);
    float* p_gate = sym(g_gate);
    float* p_sc   = sym(g_scores);
    float* p_o    = sym(g_o);

    const int NEL = ROWS * CA;

    // pair bias first (independent of everything else)
    {
        dim3 g(II / 64, ROWS);
        pairbias_kernel<<<g, 256>>>(z_ij, beta_ij, lnb_w, lnb_b, Wb, p_sc);
    }

    // LayerNorms
    ln_kernel<<<ROWS, 256>>>(a_i, nullptr, nullptr, p_aln, CA);
    ln_kernel<<<ROWS, 256>>>(s_i, lns_w, lns_b, p_sln, CS);

    // AdaLN pair + output gate, all K=384, one batched launch
    {
        GemmBatch gb = {};
        gb.j[0] = { p_sln, Ws,     bs,      nullptr, p_t1,   0 };
        gb.j[1] = { p_sln, Wnb,    nullptr, nullptr, p_t2,   0 };
        gb.j[2] = { s_i,   Ws_out, bs_out,  nullptr, p_gate, 1 };
        dim3 g(CA / 64, ROWS / 128, 3);
        gemm_tc_kernel<<<g, 256>>>(gb, ROWS, CA, CS);
    }
    adaln_ew_kernel<<<(NEL + 255) / 256, 256>>>(p_t1, p_t2, p_aln, p_a2, NEL);

    // projections q,k,v,g (K=768)
    {
        GemmBatch gb = {};
        gb.j[0] = { p_a2, Wq, bq,      nullptr, p_q, 0 };
        gb.j[1] = { p_a2, Wk, nullptr, nullptr, p_k, 0 };
        gb.j[2] = { p_a2, Wv, nullptr, nullptr, p_v, 0 };
        gb.j[3] = { p_a2, Wg, nullptr, nullptr, p_g, 0 };
        dim3 g(HC / 64, ROWS / 128, 4);
        gemm_tc_kernel<<<g, 256>>>(gb, ROWS, HC, CA);
    }

    // scores += qk/sqrt(D)
    {
        dim3 g(II / 64, II / 64, BB * HH);
        qk_tc_kernel<<<g, 128>>>(p_q, p_k, p_sc);
    }

    // softmax + AV (tensor core) + gate
    {
        dim3 g(II / 16, BB * HH);
        softmax_av_tc_kernel<<<g, 192>>>(p_sc, p_v, p_g, p_o);
    }

    // out = gate * (o @ Wo)
    {
        GemmBatch gb = {};
        gb.j[0] = { p_o, Wo, nullptr, p_gate, out, 0 };
        dim3 g(CA / 64, ROWS / 128, 1);
        gemm_tc_kernel<<<g, 256>>>(gb, ROWS, CA, HC);
    }
}

// round 13
// speedup vs baseline: 1.3511x; 1.1783x over previous
#include <cuda_runtime.h>
#include <cuda_bf16.h>
#include <math.h>

// Problem constants
#define BB 2
#define II 768
#define CA 768
#define CS 384
#define CZ 128
#define HH 16
#define DD 48
#define HC 768
#define ROWS (BB*II)          // 1536
#define EPS 1e-5f

// ---------------- device scratch (no allocations allowed) ----------------
__device__ float g_aln  [ROWS*CA];
__device__ float g_sln  [ROWS*CS];
__device__ float g_t1   [ROWS*CA];
__device__ float g_t2   [ROWS*CA];
__device__ float g_a2   [ROWS*CA];
__device__ float g_q    [ROWS*HC];
__device__ float g_k    [ROWS*HC];
__device__ float g_v    [ROWS*HC];
__device__ float g_gbuf [ROWS*HC];
__device__ float g_gate [ROWS*CA];
__device__ float g_scores[(size_t)BB*HH*II*II];   // [b][h][i][j]  ~75.5 MB
__device__ float g_o    [ROWS*HC];

// ---------------- tf32 helpers (qk path) ----------------
__device__ __forceinline__ unsigned f2tf(float x) {
    unsigned u;
    asm("cvt.rna.tf32.f32 %0, %1;" : "=r"(u) : "f"(x));
    return u;
}
__device__ __forceinline__ float tf32r(float x) {
    return __uint_as_float(f2tf(x));
}

__device__ __forceinline__ void mma_tf32(float* d, const unsigned* a, const unsigned* b) {
    asm volatile(
        "mma.sync.aligned.m16n8k8.row.col.f32.tf32.tf32.f32 "
        "{%0,%1,%2,%3}, {%4,%5,%6,%7}, {%8,%9}, {%0,%1,%2,%3};"
        : "+f"(d[0]), "+f"(d[1]), "+f"(d[2]), "+f"(d[3])
        : "r"(a[0]), "r"(a[1]), "r"(a[2]), "r"(a[3]), "r"(b[0]), "r"(b[1]));
}

// ---------------- bf16 helpers (dense gemm path) ----------------
__device__ __forceinline__ void mma_bf16(float* d, const unsigned* a, const unsigned* b) {
    asm volatile(
        "mma.sync.aligned.m16n8k16.row.col.f32.bf16.bf16.f32 "
        "{%0,%1,%2,%3}, {%4,%5,%6,%7}, {%8,%9}, {%0,%1,%2,%3};"
        : "+f"(d[0]), "+f"(d[1]), "+f"(d[2]), "+f"(d[3])
        : "r"(a[0]), "r"(a[1]), "r"(a[2]), "r"(a[3]), "r"(b[0]), "r"(b[1]));
}

// pack two floats (x_lo = even k, x_hi = odd k) into bf16x2 hi/lo planes
__device__ __forceinline__ void bf16_split2(float x_lo, float x_hi,
                                            unsigned& hw, unsigned& lw)
{
    asm("cvt.rn.bf16x2.f32 %0, %1, %2;" : "=r"(hw) : "f"(x_hi), "f"(x_lo));
    float h_lo = __uint_as_float(hw << 16);
    float h_hi = __uint_as_float(hw & 0xffff0000u);
    asm("cvt.rn.bf16x2.f32 %0, %1, %2;" : "=r"(lw) : "f"(x_hi - h_hi), "f"(x_lo - h_lo));
}

// One 16-deep K slice, bf16x3: 2 m-tiles x 4 n-tiles of m16n8k16.
// A plane layout [kword(8)][m], B plane [kword(8)][n]; strides ≡8 mod 32.
template<int SA, int SB>
__device__ __forceinline__ void do_mma16(const unsigned* AhP, const unsigned* AlP,
                                         const unsigned* BhP, const unsigned* BlP,
                                         int wm, int wn, int l4, int g,
                                         float acc[2][4][4])
{
    unsigned ah[2][4], al[2][4], bh[4][2], bl[4][2];
    const unsigned* r0 = AhP + l4 * SA;
    const unsigned* r1 = AhP + (l4 + 4) * SA;
    const unsigned* s0 = AlP + l4 * SA;
    const unsigned* s1 = AlP + (l4 + 4) * SA;
    #pragma unroll
    for (int mt = 0; mt < 2; mt++) {
        int mm = wm + mt * 16;
        ah[mt][0] = r0[mm + g];
        ah[mt][1] = r0[mm + g + 8];
        ah[mt][2] = r1[mm + g];
        ah[mt][3] = r1[mm + g + 8];
        al[mt][0] = s0[mm + g];
        al[mt][1] = s0[mm + g + 8];
        al[mt][2] = s1[mm + g];
        al[mt][3] = s1[mm + g + 8];
    }
    const unsigned* t0 = BhP + l4 * SB;
    const unsigned* t1 = BhP + (l4 + 4) * SB;
    const unsigned* u0 = BlP + l4 * SB;
    const unsigned* u1 = BlP + (l4 + 4) * SB;
    #pragma unroll
    for (int nt = 0; nt < 4; nt++) {
        int nn = wn + nt * 8 + g;
        bh[nt][0] = t0[nn];
        bh[nt][1] = t1[nn];
        bl[nt][0] = u0[nn];
        bl[nt][1] = u1[nn];
    }
    #pragma unroll
    for (int mt = 0; mt < 2; mt++)
        #pragma unroll
        for (int nt = 0; nt < 4; nt++) {
            mma_bf16(acc[mt][nt], ah[mt], bh[nt]);
            mma_bf16(acc[mt][nt], ah[mt], bl[nt]);
            mma_bf16(acc[mt][nt], al[mt], bh[nt]);
        }
}

// ---------------- LayerNorm over rows ----------------
__global__ void ln_kernel(const float* __restrict__ x,
                          const float* __restrict__ w,
                          const float* __restrict__ b,
                          float* __restrict__ y, int C)
{
    int row = blockIdx.x;
    const float* xr = x + (size_t)row * C;
    float s1 = 0.f, s2 = 0.f;
    for (int c = threadIdx.x; c < C; c += blockDim.x) {
        float v = xr[c]; s1 += v; s2 += v * v;
    }
    __shared__ float red[64];
    #pragma unroll
    for (int o = 16; o; o >>= 1) {
        s1 += __shfl_xor_sync(0xffffffffu, s1, o);
        s2 += __shfl_xor_sync(0xffffffffu, s2, o);
    }
    int wid = threadIdx.x >> 5, lid = threadIdx.x & 31;
    if (lid == 0) { red[wid] = s1; red[wid + 32] = s2; }
    __syncthreads();
    if (wid == 0) {
        s1 = (lid < (blockDim.x >> 5)) ? red[lid] : 0.f;
        s2 = (lid < (blockDim.x >> 5)) ? red[lid + 32] : 0.f;
        #pragma unroll
        for (int o = 16; o; o >>= 1) {
            s1 += __shfl_xor_sync(0xffffffffu, s1, o);
            s2 += __shfl_xor_sync(0xffffffffu, s2, o);
        }
        if (lid == 0) { red[0] = s1; red[1] = s2; }
    }
    __syncthreads();
    float mean = red[0] / C;
    float var  = red[1] / C - mean * mean;
    float rs   = rsqrtf(var + EPS);
    float* yr = y + (size_t)row * C;
    for (int c = threadIdx.x; c < C; c += blockDim.x) {
        float v = (xr[c] - mean) * rs;
        if (w) v = v * w[c] + b[c];
        yr[c] = v;
    }
}

// ---------------- bf16x3 tensor-core GEMM, batched over blockIdx.z --------
struct GemmJob { const float* A; const float* W; const float* bias;
                 const float* mul; float* out; int sig; };
struct GemmBatch { GemmJob j[4]; };

// C = A[M,K] @ W[K,N]; tile 128x64, 256 threads (8 warps, 4x2), warp tile 32x32.
// K in 16-deep tiles, bf16 hi/lo planes, double-buffered, one sync per tile.
__global__ void __launch_bounds__(256)
gemm_tc_kernel(GemmBatch batch, int M, int N, int K)
{
    __shared__ unsigned Ah[2][8][136], Al[2][8][136];   // [kword][m]
    __shared__ unsigned Bh[2][8][72],  Bl[2][8][72];    // [kword][n]

    GemmJob jb = batch.j[blockIdx.z];
    const float* __restrict__ A = jb.A;
    const float* __restrict__ W = jb.W;

    int t = threadIdx.x;
    int m0 = blockIdx.y * 128, n0 = blockIdx.x * 64;
    int w = t >> 5, lane = t & 31;
    int wm = (w >> 1) * 32, wn = (w & 1) * 32;
    int l4 = lane & 3, g = lane >> 2;

    // A loader: thread covers 8 consecutive k of one row -> 4 kwords
    int am = t >> 1, awb = (t & 1) * 4;        // kword base 0 or 4
    const float* Ap = A + (size_t)(m0 + am) * K + (t & 1) * 8;
    // B loader: thread covers k-pair (2 rows) x 2 n columns -> 2 kwords x 2 cols
    int bw = t >> 5, bn = (t & 31) * 2;        // kword row 0..7, n col
    const float* Wp0 = W + (size_t)(bw * 2)     * N + n0 + bn;
    const float* Wp1 = W + (size_t)(bw * 2 + 1) * N + n0 + bn;

    float acc[2][4][4] = {};
    int nkt = K >> 4;

    float4 a0 = *(const float4*)Ap;
    float4 a1 = *(const float4*)(Ap + 4);
    float2 bv0 = *(const float2*)Wp0;
    float2 bv1 = *(const float2*)Wp1;

    for (int kt = 0; kt < nkt; kt++) {
        int p = kt & 1;
        {   // stage current tile into buffer p (bf16 hi/lo split once)
            float av[8] = {a0.x,a0.y,a0.z,a0.w,a1.x,a1.y,a1.z,a1.w};
            #pragma unroll
            for (int i = 0; i < 4; i++) {
                unsigned hw, lw;
                bf16_split2(av[2*i], av[2*i+1], hw, lw);
                Ah[p][awb + i][am] = hw;
                Al[p][awb + i][am] = lw;
            }
            unsigned h0, l0, h1, l1;
            bf16_split2(bv0.x, bv1.x, h0, l0);   // (k even, k odd) col bn
            bf16_split2(bv0.y, bv1.y, h1, l1);   // col bn+1
            *(uint2*)&Bh[p][bw][bn] = make_uint2(h0, h1);
            *(uint2*)&Bl[p][bw][bn] = make_uint2(l0, l1);
        }
        __syncthreads();
        if (kt + 1 < nkt) {     // prefetch next tile (overlaps mma)
            const float* Ap2 = Ap + (size_t)(kt + 1) * 16;
            a0 = *(const float4*)Ap2;
            a1 = *(const float4*)(Ap2 + 4);
            bv0 = *(const float2*)(Wp0 + (size_t)(kt + 1) * 16 * N);
            bv1 = *(const float2*)(Wp1 + (size_t)(kt + 1) * 16 * N);
        }
        do_mma16<136, 72>(&Ah[p][0][0], &Al[p][0][0], &Bh[p][0][0], &Bl[p][0][0],
                          wm, wn, l4, g, acc);
    }

    // epilogue
    const float* bias = jb.bias;
    const float* mul  = jb.mul;
    float* out = jb.out;
    int sig = jb.sig;
    #pragma unroll
    for (int mt = 0; mt < 2; mt++)
        #pragma unroll
        for (int nt = 0; nt < 4; nt++) {
            int n = n0 + wn + nt * 8 + l4 * 2;
            float bx = 0.f, by = 0.f;
            if (bias) { bx = bias[n]; by = bias[n + 1]; }
            #pragma unroll
            for (int half = 0; half < 2; half++) {
                int m = m0 + wm + mt * 16 + g + half * 8;
                float x = acc[mt][nt][half * 2]     + bx;
                float y = acc[mt][nt][half * 2 + 1] + by;
                if (sig) {
                    x = 1.f / (1.f + __expf(-x));
                    y = 1.f / (1.f + __expf(-y));
                }
                if (mul) {
                    float2 mv = *(const float2*)&mul[(size_t)m * N + n];
                    x *= mv.x; y *= mv.y;
                }
                *(float2*)&out[(size_t)m * N + n] = make_float2(x, y);
            }
        }
}

// ---------------- elementwise ----------------
__global__ void adaln_ew_kernel(const float* __restrict__ t1,
                                const float* __restrict__ t2,
                                const float* __restrict__ aln,
                                float* __restrict__ a2, int n)
{
    int i = blockIdx.x * blockDim.x + threadIdx.x;
    if (i < n) {
        float s = 1.f / (1.f + __expf(-t1[i]));
        a2[i] = s * aln[i] + t2[i];
    }
}

// ---------------- pair bias (scalar, proven): scores = LN(z)@Wb + beta ----
__global__ void __launch_bounds__(256)
pairbias_kernel(const float* __restrict__ z,
                const float* __restrict__ beta,
                const float* __restrict__ lnb_w,
                const float* __restrict__ lnb_b,
                const float* __restrict__ Wb,
                float* __restrict__ scores)
{
    __shared__ __align__(16) float4 zt4[64][33];   // 64 rows x 128 c (pad 132 floats)
    __shared__ __align__(16) float  wb2[128][16];  // lnb_w[c]*Wb[c][h]
    __shared__ float  bt[64*16];                   // beta tile, xor-swizzled
    __shared__ float  colsum[16], consth[16];
    __shared__ float  mean_s[64], rs_s[64];
    __shared__ float  ps1[64][4], ps2[64][4];

    int t  = threadIdx.x;
    int j0 = blockIdx.x * 64;
    int bi = blockIdx.y;
    int b  = bi / II, i = bi % II;

    for (int e = t; e < 128 * 16; e += 256) {
        int c = e >> 4, h = e & 15;
        wb2[c][h] = lnb_w[c] * Wb[c * 16 + h];
    }
    {
        const float4* bg = (const float4*)(beta + ((size_t)bi * II + j0) * HH);
        float4 v = bg[t];
        int e = t * 4;
        int j = e >> 4, h = e & 15;
        bt[j*16 + ((h+0 + j) & 15)] = v.x;
        bt[j*16 + ((h+1 + j) & 15)] = v.y;
        bt[j*16 + ((h+2 + j) & 15)] = v.z;
        bt[j*16 + ((h+3 + j) & 15)] = v.w;
    }
    {
        const float4* zg = (const float4*)(z + ((size_t)bi * II + j0) * CZ);
        #pragma unroll
        for (int e = t; e < 2048; e += 256) {
            int r = e >> 5, q = e & 31;
            zt4[r][q] = zg[(size_t)r * 32 + q];
        }
    }
    __syncthreads();

    {
        int srow = t >> 2, seg = t & 3;
        const float* zr = (const float*)zt4[srow];
        float s1 = 0.f, s2 = 0.f;
        #pragma unroll
        for (int u = 0; u < 32; u++) {
            float v = zr[seg * 32 + u];
            s1 += v; s2 += v * v;
        }
        ps1[srow][seg] = s1; ps2[srow][seg] = s2;
    }
    if (t < 16) {
        float cs = 0.f, ch = 0.f;
        for (int c = 0; c < 128; c++) {
            cs += wb2[c][t];
            ch += lnb_b[c] * Wb[c * 16 + t];
        }
        colsum[t] = cs; consth[t] = ch;
    }
    __syncthreads();
    if (t < 64) {
        float a  = ps1[t][0] + ps1[t][1] + ps1[t][2] + ps1[t][3];
        float b2 = ps2[t][0] + ps2[t][1] + ps2[t][2] + ps2[t][3];
        float m  = a * (1.f / 128.f);
        float var = b2 * (1.f / 128.f) - m * m;
        mean_s[t] = m;
        rs_s[t]   = rsqrtf(var + EPS);
    }

    int crow = t & 63, part = t >> 6;
    float acc[16] = {};
    {
        const float4* zr = zt4[crow];
        #pragma unroll
        for (int cc = 0; cc < 8; cc++) {
            int c4 = part * 8 + cc;
            float4 z4 = zr[c4];
            #pragma unroll
            for (int u = 0; u < 4; u++) {
                float zc = (u == 0) ? z4.x : (u == 1) ? z4.y : (u == 2) ? z4.z : z4.w;
                const float4* wr = (const float4*)wb2[c4 * 4 + u];
                #pragma unroll
                for (int hq = 0; hq < 4; hq++) {
                    float4 w = wr[hq];
                    acc[hq*4+0] += zc * w.x;
                    acc[hq*4+1] += zc * w.y;
                    acc[hq*4+2] += zc * w.z;
                    acc[hq*4+3] += zc * w.w;
                }
            }
        }
    }
    __syncthreads();                    // all zt reads done; alias zt as pacc
    float* pacc = (float*)zt4;          // [4][64][17]
    {
        int base = (part * 64 + crow) * 17;
        #pragma unroll
        for (int h = 0; h < 16; h++) pacc[base + h] = acc[h];
    }
    __syncthreads();

    {
        int j = t & 63, hb = t >> 6;
        float mean = mean_s[j], rs = rs_s[j];
        #pragma unroll
        for (int u = 0; u < 4; u++) {
            int h = hb * 4 + u;
            float v = pacc[(0*64 + j)*17 + h] + pacc[(1*64 + j)*17 + h]
                    + pacc[(2*64 + j)*17 + h] + pacc[(3*64 + j)*17 + h];
            v = rs * (v - mean * colsum[h]) + consth[h] + bt[j*16 + ((h + j) & 15)];
            scores[(((size_t)(b*16 + h)) * II + i) * II + j0 + j] = v;
        }
    }
}

// ---------------- scores += q.k/sqrt(D), tf32 tensor-core ------------------
__global__ void __launch_bounds__(128)
qk_tc_kernel(const float* __restrict__ q, const float* __restrict__ k,
             float* __restrict__ scores)
{
    __shared__ float Qh[24][72], Ql[24][72], Kh[24][72], Kl[24][72];
    int bh = blockIdx.z, b = bh >> 4, h = bh & 15;
    int i0 = blockIdx.y * 64, j0 = blockIdx.x * 64;
    int t = threadIdx.x, w = t >> 5, lane = t & 31;
    int wm = (w >> 1) * 32, wn = (w & 1) * 32;
    int l4 = lane & 3, g = lane >> 2;

    float acc[2][4][4] = {};

    #pragma unroll
    for (int ph = 0; ph < 2; ph++) {
        {
            int row = t & 63, which = t >> 6;
            const float* src = (which ? k : q)
                + (((size_t)b * II + (which ? j0 : i0) + row) * HH + h) * DD + ph * 24;
            float (*Sh)[72] = which ? Kh : Qh;
            float (*Sl)[72] = which ? Kl : Ql;
            #pragma unroll
            for (int u = 0; u < 24; u += 4) {
                float4 v = *(const float4*)(src + u);
                float vv[4] = {v.x, v.y, v.z, v.w};
                #pragma unroll
                for (int c = 0; c < 4; c++) {
                    float hi = tf32r(vv[c]);
                    Sh[u + c][row] = hi;
                    Sl[u + c][row] = tf32r(vv[c] - hi);
                }
            }
        }
        __syncthreads();
        // 3 x 8-deep tf32 slices
        #pragma unroll
        for (int ks = 0; ks < 3; ks++) {
            int kk = ks * 8;
            unsigned ah[2][4], al[2][4], bh2[4][2], bl2[4][2];
            #pragma unroll
            for (int mt = 0; mt < 2; mt++) {
                int mm = wm + mt * 16;
                ah[mt][0] = __float_as_uint(Qh[kk + l4][mm + g]);
                ah[mt][1] = __float_as_uint(Qh[kk + l4][mm + g + 8]);
                ah[mt][2] = __float_as_uint(Qh[kk + l4 + 4][mm + g]);
                ah[mt][3] = __float_as_uint(Qh[kk + l4 + 4][mm + g + 8]);
                al[mt][0] = __float_as_uint(Ql[kk + l4][mm + g]);
                al[mt][1] = __float_as_uint(Ql[kk + l4][mm + g + 8]);
                al[mt][2] = __float_as_uint(Ql[kk + l4 + 4][mm + g]);
                al[mt][3] = __float_as_uint(Ql[kk + l4 + 4][mm + g + 8]);
            }
            #pragma unroll
            for (int nt = 0; nt < 4; nt++) {
                int nn = wn + nt * 8 + g;
                bh2[nt][0] = __float_as_uint(Kh[kk + l4][nn]);
                bh2[nt][1] = __float_as_uint(Kh[kk + l4 + 4][nn]);
                bl2[nt][0] = __float_as_uint(Kl[kk + l4][nn]);
                bl2[nt][1] = __float_as_uint(Kl[kk + l4 + 4][nn]);
            }
            #pragma unroll
            for (int mt = 0; mt < 2; mt++)
                #pragma unroll
                for (int nt = 0; nt < 4; nt++) {
                    mma_tf32(acc[mt][nt], ah[mt], bh2[nt]);
                    mma_tf32(acc[mt][nt], ah[mt], bl2[nt]);
                    mma_tf32(acc[mt][nt], al[mt], bh2[nt]);
                }
        }
        __syncthreads();
    }

    const float sc = rsqrtf(48.f);
    #pragma unroll
    for (int mt = 0; mt < 2; mt++)
        #pragma unroll
        for (int nt = 0; nt < 4; nt++)
            #pragma unroll
            for (int half = 0; half < 2; half++) {
                int i = i0 + wm + mt * 16 + g + half * 8;
                int jj = j0 + wn + nt * 8 + l4 * 2;
                size_t idx = ((size_t)bh * II + i) * II + jj;
                float2 old = *(float2*)&scores[idx];
                old.x += acc[mt][nt][half * 2]     * sc;
                old.y += acc[mt][nt][half * 2 + 1] * sc;
                *(float2*)&scores[idx] = old;
            }
}

// ---------------- softmax over j + AV + gate (scalar, proven R6) ----------
__global__ void __launch_bounds__(192)
softmax_av_kernel(const float* __restrict__ scores,
                  const float* __restrict__ v,
                  const float* __restrict__ gbuf,
                  float* __restrict__ o)
{
    __shared__ __align__(16) float p[16][II];    // 48KB
    __shared__ __align__(16) float vt[48][36];   // [d][j] transposed
    int bh = blockIdx.y, b = bh >> 4, h = bh & 15;
    int ibase = blockIdx.x * 16;
    int t = threadIdx.x, warp = t >> 5, lane = t & 31;

    for (int r = warp; r < 16; r += 6) {
        const float* srow = &scores[(((size_t)bh * II) + ibase + r) * II];
        float mx = -1e30f;
        for (int j = lane; j < II; j += 32) {
            float s = srow[j]; p[r][j] = s; mx = fmaxf(mx, s);
        }
        #pragma unroll
        for (int off = 16; off; off >>= 1) mx = fmaxf(mx, __shfl_xor_sync(0xffffffffu, mx, off));
        float sum = 0.f;
        for (int j = lane; j < II; j += 32) {
            float e = __expf(p[r][j] - mx); p[r][j] = e; sum += e;
        }
        #pragma unroll
        for (int off = 16; off; off >>= 1) sum += __shfl_xor_sync(0xffffffffu, sum, off);
        float inv = 1.f / sum;
        for (int j = lane; j < II; j += 32) p[r][j] *= inv;
    }
    __syncthreads();

    int ia = t / 24, d0 = t % 24;
    float acc[2][2] = {};
    for (int jt = 0; jt < II / 32; jt++) {
        for (int e = t; e < 32 * 48; e += 192) {
            int jj = e / 48, d = e % 48;
            vt[d][jj] = v[(((size_t)b * II + jt * 32 + jj) * HH + h) * DD + d];
        }
        __syncthreads();
        #pragma unroll
        for (int jj = 0; jj < 32; jj += 4) {
            float4 p0 = *(const float4*)&p[ia][jt * 32 + jj];
            float4 p1 = *(const float4*)&p[ia + 8][jt * 32 + jj];
            float4 v0 = *(const float4*)&vt[d0][jj];
            float4 v1 = *(const float4*)&vt[d0 + 24][jj];
            acc[0][0] += p0.x*v0.x + p0.y*v0.y + p0.z*v0.z + p0.w*v0.w;
            acc[0][1] += p0.x*v1.x + p0.y*v1.y + p0.z*v1.z + p0.w*v1.w;
            acc[1][0] += p1.x*v0.x + p1.y*v0.y + p1.z*v0.z + p1.w*v0.w;
            acc[1][1] += p1.x*v1.x + p1.y*v1.y + p1.z*v1.z + p1.w*v1.w;
        }
        __syncthreads();
    }
    #pragma unroll
    for (int u = 0; u < 2; u++)
        #pragma unroll
        for (int w2 = 0; w2 < 2; w2++) {
            int i = ibase + ia + u * 8;
            int d = d0 + w2 * 24;
            size_t gi = (((size_t)b * II + i) * HH + h) * DD + d;
            float g = 1.f / (1.f + __expf(-gbuf[gi]));
            o[gi] = acc[u][w2] * g;
        }
}

// ---------------- host launch ----------------
static float* sym(const void* s) {
    void* p = nullptr;
    cudaGetSymbolAddress(&p, s);
    return (float*)p;
}

extern "C" void kernel_launch(void* const* d_in, const int* in_sizes, int n_in,
                              void* d_out, int out_size)
{
    const float* a_i      = (const float*)d_in[0];
    const float* s_i      = (const float*)d_in[1];
    const float* z_ij     = (const float*)d_in[2];
    const float* beta_ij  = (const float*)d_in[3];
    const float* lns_w    = (const float*)d_in[4];
    const float* lns_b    = (const float*)d_in[5];
    const float* Ws       = (const float*)d_in[6];
    const float* bs       = (const float*)d_in[7];
    const float* Wnb      = (const float*)d_in[8];
    const float* Wq       = (const float*)d_in[9];
    const float* bq       = (const float*)d_in[10];
    const float* Wk       = (const float*)d_in[11];
    const float* Wv       = (const float*)d_in[12];
    const float* lnb_w    = (const float*)d_in[13];
    const float* lnb_b    = (const float*)d_in[14];
    const float* Wb       = (const float*)d_in[15];
    const float* Wg       = (const float*)d_in[16];
    const float* Wo       = (const float*)d_in[17];
    const float* Ws_out   = (const float*)d_in[18];
    const float* bs_out   = (const float*)d_in[19];
    float* out = (float*)d_out;

    float* p_aln  = sym(g_aln);
    float* p_sln  = sym(g_sln);
    float* p_t1   = sym(g_t1);
    float* p_t2   = sym(g_t2);
    float* p_a2   = sym(g_a2);
    float* p_q    = sym(g_q);
    float* p_k    = sym(g_k);
    float* p_v    = sym(g_v);
    float* p_g    = sym(g_gbuf);
    float* p_gate = sym(g_gate);
    float* p_sc   = sym(g_scores);
    float* p_o    = sym(g_o);

    const int NEL = ROWS * CA;

    // pair bias first (independent of everything else)
    {
        dim3 g(II / 64, ROWS);
        pairbias_kernel<<<g, 256>>>(z_ij, beta_ij, lnb_w, lnb_b, Wb, p_sc);
    }

    // LayerNorms
    ln_kernel<<<ROWS, 256>>>(a_i, nullptr, nullptr, p_aln, CA);
    ln_kernel<<<ROWS, 256>>>(s_i, lns_w, lns_b, p_sln, CS);

    // AdaLN pair + output gate, all K=384, one batched launch
    {
        GemmBatch gb = {};
        gb.j[0] = { p_sln, Ws,     bs,      nullptr, p_t1,   0 };
        gb.j[1] = { p_sln, Wnb,    nullptr, nullptr, p_t2,   0 };
        gb.j[2] = { s_i,   Ws_out, bs_out,  nullptr, p_gate, 1 };
        dim3 g(CA / 64, ROWS / 128, 3);
        gemm_tc_kernel<<<g, 256>>>(gb, ROWS, CA, CS);
    }
    adaln_ew_kernel<<<(NEL + 255) / 256, 256>>>(p_t1, p_t2, p_aln, p_a2, NEL);

    // projections q,k,v,g (K=768)
    {
        GemmBatch gb = {};
        gb.j[0] = { p_a2, Wq, bq,      nullptr, p_q, 0 };
        gb.j[1] = { p_a2, Wk, nullptr, nullptr, p_k, 0 };
        gb.j[2] = { p_a2, Wv, nullptr, nullptr, p_v, 0 };
        gb.j[3] = { p_a2, Wg, nullptr, nullptr, p_g, 0 };
        dim3 g(HC / 64, ROWS / 128, 4);
        gemm_tc_kernel<<<g, 256>>>(gb, ROWS, HC, CA);
    }

    // scores += qk/sqrt(D)
    {
        dim3 g(II / 64, II / 64, BB * HH);
        qk_tc_kernel<<<g, 128>>>(p_q, p_k, p_sc);
    }

    // softmax + AV + gate (scalar, proven)
    {
        dim3 g(II / 16, BB * HH);
        softmax_av_kernel<<<g, 192>>>(p_sc, p_v, p_g, p_o);
    }

    // out = gate * (o @ Wo)
    {
        GemmBatch gb = {};
        gb.j[0] = { p_o, Wo, nullptr, p_gate, out, 0 };
        dim3 g(CA / 64, ROWS / 128, 1);
        gemm_tc_kernel<<<g, 256>>>(gb, ROWS, CA, HC);
    }
}

// round 15
// speedup vs baseline: 1.5135x; 1.1202x over previous
#include <cuda_runtime.h>
#include <cuda_bf16.h>
#include <math.h>

// Problem constants
#define BB 2
#define II 768
#define CA 768
#define CS 384
#define CZ 128
#define HH 16
#define DD 48
#define HC 768
#define ROWS (BB*II)          // 1536
#define EPS 1e-5f

// ---------------- device scratch (no allocations allowed) ----------------
__device__ float g_aln  [ROWS*CA];
__device__ float g_sln  [ROWS*CS];
__device__ float g_t1   [ROWS*CA];
__device__ float g_t2   [ROWS*CA];
__device__ float g_a2   [ROWS*CA];
__device__ float g_q    [ROWS*HC];
__device__ float g_k    [ROWS*HC];
__device__ float g_v    [ROWS*HC];
__device__ float g_gbuf [ROWS*HC];
__device__ float g_gate [ROWS*CA];
__device__ float g_scores[(size_t)BB*HH*II*II];   // [b][h][i][j]  ~75.5 MB
__device__ float g_o    [ROWS*HC];

// ---------------- tf32 helpers (qk path) ----------------
__device__ __forceinline__ unsigned f2tf(float x) {
    unsigned u;
    asm("cvt.rna.tf32.f32 %0, %1;" : "=r"(u) : "f"(x));
    return u;
}
__device__ __forceinline__ float tf32r(float x) {
    return __uint_as_float(f2tf(x));
}

__device__ __forceinline__ void mma_tf32(float* d, const unsigned* a, const unsigned* b) {
    asm volatile(
        "mma.sync.aligned.m16n8k8.row.col.f32.tf32.tf32.f32 "
        "{%0,%1,%2,%3}, {%4,%5,%6,%7}, {%8,%9}, {%0,%1,%2,%3};"
        : "+f"(d[0]), "+f"(d[1]), "+f"(d[2]), "+f"(d[3])
        : "r"(a[0]), "r"(a[1]), "r"(a[2]), "r"(a[3]), "r"(b[0]), "r"(b[1]));
}

// ---------------- bf16 helpers ----------------
__device__ __forceinline__ void mma_bf16(float* d, const unsigned* a, const unsigned* b) {
    asm volatile(
        "mma.sync.aligned.m16n8k16.row.col.f32.bf16.bf16.f32 "
        "{%0,%1,%2,%3}, {%4,%5,%6,%7}, {%8,%9}, {%0,%1,%2,%3};"
        : "+f"(d[0]), "+f"(d[1]), "+f"(d[2]), "+f"(d[3])
        : "r"(a[0]), "r"(a[1]), "r"(a[2]), "r"(a[3]), "r"(b[0]), "r"(b[1]));
}

// pack two floats (x_lo = even k, x_hi = odd k) into bf16x2 hi/lo planes
__device__ __forceinline__ void bf16_split2(float x_lo, float x_hi,
                                            unsigned& hw, unsigned& lw)
{
    asm("cvt.rn.bf16x2.f32 %0, %1, %2;" : "=r"(hw) : "f"(x_hi), "f"(x_lo));
    float h_lo = __uint_as_float(hw << 16);
    float h_hi = __uint_as_float(hw & 0xffff0000u);
    asm("cvt.rn.bf16x2.f32 %0, %1, %2;" : "=r"(lw) : "f"(x_hi - h_hi), "f"(x_lo - h_lo));
}

// One 16-deep K slice, bf16x3: 2 m-tiles x 4 n-tiles of m16n8k16.
// A plane layout [kword(8)][m], B plane [kword(8)][n]; strides ≡8 mod 32.
template<int SA, int SB>
__device__ __forceinline__ void do_mma16(const unsigned* AhP, const unsigned* AlP,
                                         const unsigned* BhP, const unsigned* BlP,
                                         int wm, int wn, int l4, int g,
                                         float acc[2][4][4])
{
    unsigned ah[2][4], al[2][4], bh[4][2], bl[4][2];
    const unsigned* r0 = AhP + l4 * SA;
    const unsigned* r1 = AhP + (l4 + 4) * SA;
    const unsigned* s0 = AlP + l4 * SA;
    const unsigned* s1 = AlP + (l4 + 4) * SA;
    #pragma unroll
    for (int mt = 0; mt < 2; mt++) {
        int mm = wm + mt * 16;
        ah[mt][0] = r0[mm + g];
        ah[mt][1] = r0[mm + g + 8];
        ah[mt][2] = r1[mm + g];
        ah[mt][3] = r1[mm + g + 8];
        al[mt][0] = s0[mm + g];
        al[mt][1] = s0[mm + g + 8];
        al[mt][2] = s1[mm + g];
        al[mt][3] = s1[mm + g + 8];
    }
    const unsigned* t0 = BhP + l4 * SB;
    const unsigned* t1 = BhP + (l4 + 4) * SB;
    const unsigned* u0 = BlP + l4 * SB;
    const unsigned* u1 = BlP + (l4 + 4) * SB;
    #pragma unroll
    for (int nt = 0; nt < 4; nt++) {
        int nn = wn + nt * 8 + g;
        bh[nt][0] = t0[nn];
        bh[nt][1] = t1[nn];
        bl[nt][0] = u0[nn];
        bl[nt][1] = u1[nn];
    }
    #pragma unroll
    for (int mt = 0; mt < 2; mt++)
        #pragma unroll
        for (int nt = 0; nt < 4; nt++) {
            mma_bf16(acc[mt][nt], ah[mt], bh[nt]);
            mma_bf16(acc[mt][nt], ah[mt], bl[nt]);
            mma_bf16(acc[mt][nt], al[mt], bh[nt]);
        }
}

// ---------------- LayerNorm over rows ----------------
__global__ void ln_kernel(const float* __restrict__ x,
                          const float* __restrict__ w,
                          const float* __restrict__ b,
                          float* __restrict__ y, int C)
{
    int row = blockIdx.x;
    const float* xr = x + (size_t)row * C;
    float s1 = 0.f, s2 = 0.f;
    for (int c = threadIdx.x; c < C; c += blockDim.x) {
        float v = xr[c]; s1 += v; s2 += v * v;
    }
    __shared__ float red[64];
    #pragma unroll
    for (int o = 16; o; o >>= 1) {
        s1 += __shfl_xor_sync(0xffffffffu, s1, o);
        s2 += __shfl_xor_sync(0xffffffffu, s2, o);
    }
    int wid = threadIdx.x >> 5, lid = threadIdx.x & 31;
    if (lid == 0) { red[wid] = s1; red[wid + 32] = s2; }
    __syncthreads();
    if (wid == 0) {
        s1 = (lid < (blockDim.x >> 5)) ? red[lid] : 0.f;
        s2 = (lid < (blockDim.x >> 5)) ? red[lid + 32] : 0.f;
        #pragma unroll
        for (int o = 16; o; o >>= 1) {
            s1 += __shfl_xor_sync(0xffffffffu, s1, o);
            s2 += __shfl_xor_sync(0xffffffffu, s2, o);
        }
        if (lid == 0) { red[0] = s1; red[1] = s2; }
    }
    __syncthreads();
    float mean = red[0] / C;
    float var  = red[1] / C - mean * mean;
    float rs   = rsqrtf(var + EPS);
    float* yr = y + (size_t)row * C;
    for (int c = threadIdx.x; c < C; c += blockDim.x) {
        float v = (xr[c] - mean) * rs;
        if (w) v = v * w[c] + b[c];
        yr[c] = v;
    }
}

// ---------------- bf16x3 tensor-core GEMM, batched over blockIdx.z --------
struct GemmJob { const float* A; const float* W; const float* bias;
                 const float* mul; float* out; int sig; };
struct GemmBatch { GemmJob j[4]; };

__global__ void __launch_bounds__(256)
gemm_tc_kernel(GemmBatch batch, int M, int N, int K)
{
    __shared__ unsigned Ah[2][8][136], Al[2][8][136];   // [kword][m]
    __shared__ unsigned Bh[2][8][72],  Bl[2][8][72];    // [kword][n]

    GemmJob jb = batch.j[blockIdx.z];
    const float* __restrict__ A = jb.A;
    const float* __restrict__ W = jb.W;

    int t = threadIdx.x;
    int m0 = blockIdx.y * 128, n0 = blockIdx.x * 64;
    int w = t >> 5, lane = t & 31;
    int wm = (w >> 1) * 32, wn = (w & 1) * 32;
    int l4 = lane & 3, g = lane >> 2;

    int am = t >> 1, awb = (t & 1) * 4;
    const float* Ap = A + (size_t)(m0 + am) * K + (t & 1) * 8;
    int bw = t >> 5, bn = (t & 31) * 2;
    const float* Wp0 = W + (size_t)(bw * 2)     * N + n0 + bn;
    const float* Wp1 = W + (size_t)(bw * 2 + 1) * N + n0 + bn;

    float acc[2][4][4] = {};
    int nkt = K >> 4;

    float4 a0 = *(const float4*)Ap;
    float4 a1 = *(const float4*)(Ap + 4);
    float2 bv0 = *(const float2*)Wp0;
    float2 bv1 = *(const float2*)Wp1;

    for (int kt = 0; kt < nkt; kt++) {
        int p = kt & 1;
        {
            float av[8] = {a0.x,a0.y,a0.z,a0.w,a1.x,a1.y,a1.z,a1.w};
            #pragma unroll
            for (int i = 0; i < 4; i++) {
                unsigned hw, lw;
                bf16_split2(av[2*i], av[2*i+1], hw, lw);
                Ah[p][awb + i][am] = hw;
                Al[p][awb + i][am] = lw;
            }
            unsigned h0, l0, h1, l1;
            bf16_split2(bv0.x, bv1.x, h0, l0);
            bf16_split2(bv0.y, bv1.y, h1, l1);
            *(uint2*)&Bh[p][bw][bn] = make_uint2(h0, h1);
            *(uint2*)&Bl[p][bw][bn] = make_uint2(l0, l1);
        }
        __syncthreads();
        if (kt + 1 < nkt) {
            const float* Ap2 = Ap + (size_t)(kt + 1) * 16;
            a0 = *(const float4*)Ap2;
            a1 = *(const float4*)(Ap2 + 4);
            bv0 = *(const float2*)(Wp0 + (size_t)(kt + 1) * 16 * N);
            bv1 = *(const float2*)(Wp1 + (size_t)(kt + 1) * 16 * N);
        }
        do_mma16<136, 72>(&Ah[p][0][0], &Al[p][0][0], &Bh[p][0][0], &Bl[p][0][0],
                          wm, wn, l4, g, acc);
    }

    const float* bias = jb.bias;
    const float* mul  = jb.mul;
    float* out = jb.out;
    int sig = jb.sig;
    #pragma unroll
    for (int mt = 0; mt < 2; mt++)
        #pragma unroll
        for (int nt = 0; nt < 4; nt++) {
            int n = n0 + wn + nt * 8 + l4 * 2;
            float bx = 0.f, by = 0.f;
            if (bias) { bx = bias[n]; by = bias[n + 1]; }
            #pragma unroll
            for (int half = 0; half < 2; half++) {
                int m = m0 + wm + mt * 16 + g + half * 8;
                float x = acc[mt][nt][half * 2]     + bx;
                float y = acc[mt][nt][half * 2 + 1] + by;
                if (sig) {
                    x = 1.f / (1.f + __expf(-x));
                    y = 1.f / (1.f + __expf(-y));
                }
                if (mul) {
                    float2 mv = *(const float2*)&mul[(size_t)m * N + n];
                    x *= mv.x; y *= mv.y;
                }
                *(float2*)&out[(size_t)m * N + n] = make_float2(x, y);
            }
        }
}

// ---------------- elementwise ----------------
__global__ void adaln_ew_kernel(const float* __restrict__ t1,
                                const float* __restrict__ t2,
                                const float* __restrict__ aln,
                                float* __restrict__ a2, int n)
{
    int i = blockIdx.x * blockDim.x + threadIdx.x;
    if (i < n) {
        float s = 1.f / (1.f + __expf(-t1[i]));
        a2[i] = s * aln[i] + t2[i];
    }
}

// ---------------- pair bias via bf16x3 mma: scores = LN(z)@Wb + beta ------
// Block: 64 j-rows for fixed (b,i). 256 threads = 8 warps (4 m x 2 n tiles).
// Planes: zh/zl [m=64][kw=0..63] stride 68 (≡4 mod 32 → fragment banks 4g+l4,
// all 32 distinct). Stats computed exact-fp32 from raw values at staging.
__global__ void __launch_bounds__(256)
pairbias_kernel(const float* __restrict__ z,
                const float* __restrict__ beta,
                const float* __restrict__ lnb_w,
                const float* __restrict__ lnb_b,
                const float* __restrict__ Wb,
                float* __restrict__ scores)
{
    __shared__ unsigned zh[64][68], zl[64][68];    // 34.8KB
    __shared__ unsigned wbh[16][68], wbl[16][68];  // 8.7KB
    __shared__ float ps1[64][33], ps2[64][33];     // 16.9KB
    __shared__ float bt[64*16];                    // beta, xor-swizzled
    __shared__ float colsum[16], consth[16];
    __shared__ float mean_s[64], rs_s[64];
    __shared__ float pacc[64][17];                 // 4.4KB

    int t  = threadIdx.x;
    int w  = t >> 5, lane = t & 31;
    int j0 = blockIdx.x * 64;
    int bi = blockIdx.y;
    int b  = bi / II, i = bi % II;

    // --- stage z tile: split to bf16 planes + exact row-stat partials ---
    {
        const float4* zg = (const float4*)(z + ((size_t)bi * II + j0) * CZ);
        #pragma unroll
        for (int it = 0; it < 8; it++) {
            int e = t + 256 * it;
            int r = e >> 5;                    // = w + 8*it (fixed per warp)
            float4 v = zg[(size_t)r * 32 + lane];
            unsigned hw0, lw0, hw1, lw1;
            bf16_split2(v.x, v.y, hw0, lw0);
            bf16_split2(v.z, v.w, hw1, lw1);
            *(uint2*)&zh[r][lane * 2] = make_uint2(hw0, hw1);
            *(uint2*)&zl[r][lane * 2] = make_uint2(lw0, lw1);
            ps1[r][lane] = v.x + v.y + v.z + v.w;
            ps2[r][lane] = v.x*v.x + v.y*v.y + v.z*v.z + v.w*v.w;
        }
    }
    // --- stage wb planes: w2 = lnb_w*Wb, split once ---
    {
        int h = t & 15, kb = (t >> 4) * 4;
        #pragma unroll
        for (int u = 0; u < 4; u++) {
            int c = (kb + u) * 2;
            float w0 = lnb_w[c]     * Wb[c * 16 + h];
            float w1 = lnb_w[c + 1] * Wb[(c + 1) * 16 + h];
            unsigned hw, lw;
            bf16_split2(w0, w1, hw, lw);
            wbh[h][kb + u] = hw;
            wbl[h][kb + u] = lw;
        }
    }
    // --- stage beta tile (xor-swizzled, proven) ---
    {
        const float4* bg = (const float4*)(beta + ((size_t)bi * II + j0) * HH);
        float4 v = bg[t];
        int e = t * 4;
        int j = e >> 4, h = e & 15;
        bt[j*16 + ((h+0 + j) & 15)] = v.x;
        bt[j*16 + ((h+1 + j) & 15)] = v.y;
        bt[j*16 + ((h+2 + j) & 15)] = v.z;
        bt[j*16 + ((h+3 + j) & 15)] = v.w;
    }
    // --- colsum / consth in exact fp32 (gmem, L1-cached) ---
    if (t < 16) {
        float cs = 0.f, ch = 0.f;
        for (int c = 0; c < 128; c++) {
            cs += lnb_w[c] * Wb[c * 16 + t];
            ch += lnb_b[c] * Wb[c * 16 + t];
        }
        colsum[t] = cs; consth[t] = ch;
    }
    __syncthreads();

    // --- finish row stats ---
    if (t < 64) {
        float a = 0.f, b2 = 0.f;
        #pragma unroll
        for (int l = 0; l < 32; l++) { a += ps1[t][l]; b2 += ps2[t][l]; }
        float m  = a * (1.f / 128.f);
        float var = b2 * (1.f / 128.f) - m * m;
        mean_s[t] = m;
        rs_s[t]   = rsqrtf(var + EPS);
    }

    // --- mma: dot[j][h], K=128 in 8 k16-tiles, bf16x3 ---
    int g2 = lane >> 2, l4 = lane & 3;
    int wm = (w >> 1) * 16, wn = (w & 1) * 8;
    float acc[4] = {0.f, 0.f, 0.f, 0.f};
    const unsigned* zh0 = &zh[wm + g2][0];
    const unsigned* zh1 = &zh[wm + g2 + 8][0];
    const unsigned* zl0 = &zl[wm + g2][0];
    const unsigned* zl1 = &zl[wm + g2 + 8][0];
    const unsigned* wh0 = &wbh[wn + g2][0];
    const unsigned* wl0 = &wbl[wn + g2][0];
    #pragma unroll
    for (int kt = 0; kt < 8; kt++) {
        int kb = kt * 8;
        unsigned ah[4], al[4], bh2[2], bl2[2];
        ah[0] = zh0[kb + l4];
        ah[1] = zh1[kb + l4];
        ah[2] = zh0[kb + l4 + 4];
        ah[3] = zh1[kb + l4 + 4];
        al[0] = zl0[kb + l4];
        al[1] = zl1[kb + l4];
        al[2] = zl0[kb + l4 + 4];
        al[3] = zl1[kb + l4 + 4];
        bh2[0] = wh0[kb + l4];
        bh2[1] = wh0[kb + l4 + 4];
        bl2[0] = wl0[kb + l4];
        bl2[1] = wl0[kb + l4 + 4];
        mma_bf16(acc, ah, bh2);
        mma_bf16(acc, ah, bl2);
        mma_bf16(acc, al, bh2);
    }

    // --- park accumulators for coalesced epilogue ---
    pacc[wm + g2][wn + 2 * l4]         = acc[0];
    pacc[wm + g2][wn + 2 * l4 + 1]     = acc[1];
    pacc[wm + g2 + 8][wn + 2 * l4]     = acc[2];
    pacc[wm + g2 + 8][wn + 2 * l4 + 1] = acc[3];
    __syncthreads();

    // --- epilogue: LN closed form + beta; coalesced score writes ---
    {
        int j = t & 63, hb = t >> 6;
        float mean = mean_s[j], rs = rs_s[j];
        #pragma unroll
        for (int u = 0; u < 4; u++) {
            int h = hb * 4 + u;
            float v = pacc[j][h];
            v = rs * (v - mean * colsum[h]) + consth[h] + bt[j*16 + ((h + j) & 15)];
            scores[(((size_t)(b*16 + h)) * II + i) * II + j0 + j] = v;
        }
    }
}

// ---------------- scores += q.k/sqrt(D), tf32 tensor-core ------------------
__global__ void __launch_bounds__(128)
qk_tc_kernel(const float* __restrict__ q, const float* __restrict__ k,
             float* __restrict__ scores)
{
    __shared__ float Qh[24][72], Ql[24][72], Kh[24][72], Kl[24][72];
    int bh = blockIdx.z, b = bh >> 4, h = bh & 15;
    int i0 = blockIdx.y * 64, j0 = blockIdx.x * 64;
    int t = threadIdx.x, w = t >> 5, lane = t & 31;
    int wm = (w >> 1) * 32, wn = (w & 1) * 32;
    int l4 = lane & 3, g = lane >> 2;

    float acc[2][4][4] = {};

    #pragma unroll
    for (int ph = 0; ph < 2; ph++) {
        {
            int row = t & 63, which = t >> 6;
            const float* src = (which ? k : q)
                + (((size_t)b * II + (which ? j0 : i0) + row) * HH + h) * DD + ph * 24;
            float (*Sh)[72] = which ? Kh : Qh;
            float (*Sl)[72] = which ? Kl : Ql;
            #pragma unroll
            for (int u = 0; u < 24; u += 4) {
                float4 v = *(const float4*)(src + u);
                float vv[4] = {v.x, v.y, v.z, v.w};
                #pragma unroll
                for (int c = 0; c < 4; c++) {
                    float hi = tf32r(vv[c]);
                    Sh[u + c][row] = hi;
                    Sl[u + c][row] = tf32r(vv[c] - hi);
                }
            }
        }
        __syncthreads();
        #pragma unroll
        for (int ks = 0; ks < 3; ks++) {
            int kk = ks * 8;
            unsigned ah[2][4], al[2][4], bh2[4][2], bl2[4][2];
            #pragma unroll
            for (int mt = 0; mt < 2; mt++) {
                int mm = wm + mt * 16;
                ah[mt][0] = __float_as_uint(Qh[kk + l4][mm + g]);
                ah[mt][1] = __float_as_uint(Qh[kk + l4][mm + g + 8]);
                ah[mt][2] = __float_as_uint(Qh[kk + l4 + 4][mm + g]);
                ah[mt][3] = __float_as_uint(Qh[kk + l4 + 4][mm + g + 8]);
                al[mt][0] = __float_as_uint(Ql[kk + l4][mm + g]);
                al[mt][1] = __float_as_uint(Ql[kk + l4][mm + g + 8]);
                al[mt][2] = __float_as_uint(Ql[kk + l4 + 4][mm + g]);
                al[mt][3] = __float_as_uint(Ql[kk + l4 + 4][mm + g + 8]);
            }
            #pragma unroll
            for (int nt = 0; nt < 4; nt++) {
                int nn = wn + nt * 8 + g;
                bh2[nt][0] = __float_as_uint(Kh[kk + l4][nn]);
                bh2[nt][1] = __float_as_uint(Kh[kk + l4 + 4][nn]);
                bl2[nt][0] = __float_as_uint(Kl[kk + l4][nn]);
                bl2[nt][1] = __float_as_uint(Kl[kk + l4 + 4][nn]);
            }
            #pragma unroll
            for (int mt = 0; mt < 2; mt++)
                #pragma unroll
                for (int nt = 0; nt < 4; nt++) {
                    mma_tf32(acc[mt][nt], ah[mt], bh2[nt]);
                    mma_tf32(acc[mt][nt], ah[mt], bl2[nt]);
                    mma_tf32(acc[mt][nt], al[mt], bh2[nt]);
                }
        }
        __syncthreads();
    }

    const float sc = rsqrtf(48.f);
    #pragma unroll
    for (int mt = 0; mt < 2; mt++)
        #pragma unroll
        for (int nt = 0; nt < 4; nt++)
            #pragma unroll
            for (int half = 0; half < 2; half++) {
                int i = i0 + wm + mt * 16 + g + half * 8;
                int jj = j0 + wn + nt * 8 + l4 * 2;
                size_t idx = ((size_t)bh * II + i) * II + jj;
                float2 old = *(float2*)&scores[idx];
                old.x += acc[mt][nt][half * 2]     * sc;
                old.y += acc[mt][nt][half * 2 + 1] * sc;
                *(float2*)&scores[idx] = old;
            }
}

// ---------------- softmax over j + AV + gate (scalar, proven) -------------
__global__ void __launch_bounds__(192)
softmax_av_kernel(const float* __restrict__ scores,
                  const float* __restrict__ v,
                  const float* __restrict__ gbuf,
                  float* __restrict__ o)
{
    __shared__ __align__(16) float p[16][II];    // 48KB
    __shared__ __align__(16) float vt[48][36];   // [d][j] transposed
    int bh = blockIdx.y, b = bh >> 4, h = bh & 15;
    int ibase = blockIdx.x * 16;
    int t = threadIdx.x, warp = t >> 5, lane = t & 31;

    for (int r = warp; r < 16; r += 6) {
        const float* srow = &scores[(((size_t)bh * II) + ibase + r) * II];
        float mx = -1e30f;
        for (int j = lane; j < II; j += 32) {
            float s = srow[j]; p[r][j] = s; mx = fmaxf(mx, s);
        }
        #pragma unroll
        for (int off = 16; off; off >>= 1) mx = fmaxf(mx, __shfl_xor_sync(0xffffffffu, mx, off));
        float sum = 0.f;
        for (int j = lane; j < II; j += 32) {
            float e = __expf(p[r][j] - mx); p[r][j] = e; sum += e;
        }
        #pragma unroll
        for (int off = 16; off; off >>= 1) sum += __shfl_xor_sync(0xffffffffu, sum, off);
        float inv = 1.f / sum;
        for (int j = lane; j < II; j += 32) p[r][j] *= inv;
    }
    __syncthreads();

    int ia = t / 24, d0 = t % 24;
    float acc[2][2] = {};
    for (int jt = 0; jt < II / 32; jt++) {
        for (int e = t; e < 32 * 48; e += 192) {
            int jj = e / 48, d = e % 48;
            vt[d][jj] = v[(((size_t)b * II + jt * 32 + jj) * HH + h) * DD + d];
        }
        __syncthreads();
        #pragma unroll
        for (int jj = 0; jj < 32; jj += 4) {
            float4 p0 = *(const float4*)&p[ia][jt * 32 + jj];
            float4 p1 = *(const float4*)&p[ia + 8][jt * 32 + jj];
            float4 v0 = *(const float4*)&vt[d0][jj];
            float4 v1 = *(const float4*)&vt[d0 + 24][jj];
            acc[0][0] += p0.x*v0.x + p0.y*v0.y + p0.z*v0.z + p0.w*v0.w;
            acc[0][1] += p0.x*v1.x + p0.y*v1.y + p0.z*v1.z + p0.w*v1.w;
            acc[1][0] += p1.x*v0.x + p1.y*v0.y + p1.z*v0.z + p1.w*v0.w;
            acc[1][1] += p1.x*v1.x + p1.y*v1.y + p1.z*v1.z + p1.w*v1.w;
        }
        __syncthreads();
    }
    #pragma unroll
    for (int u = 0; u < 2; u++)
        #pragma unroll
        for (int w2 = 0; w2 < 2; w2++) {
            int i = ibase + ia + u * 8;
            int d = d0 + w2 * 24;
            size_t gi = (((size_t)b * II + i) * HH + h) * DD + d;
            float g = 1.f / (1.f + __expf(-gbuf[gi]));
            o[gi] = acc[u][w2] * g;
        }
}

// ---------------- host launch ----------------
static float* sym(const void* s) {
    void* p = nullptr;
    cudaGetSymbolAddress(&p, s);
    return (float*)p;
}

extern "C" void kernel_launch(void* const* d_in, const int* in_sizes, int n_in,
                              void* d_out, int out_size)
{
    const float* a_i      = (const float*)d_in[0];
    const float* s_i      = (const float*)d_in[1];
    const float* z_ij     = (const float*)d_in[2];
    const float* beta_ij  = (const float*)d_in[3];
    const float* lns_w    = (const float*)d_in[4];
    const float* lns_b    = (const float*)d_in[5];
    const float* Ws       = (const float*)d_in[6];
    const float* bs       = (const float*)d_in[7];
    const float* Wnb      = (const float*)d_in[8];
    const float* Wq       = (const float*)d_in[9];
    const float* bq       = (const float*)d_in[10];
    const float* Wk       = (const float*)d_in[11];
    const float* Wv       = (const float*)d_in[12];
    const float* lnb_w    = (const float*)d_in[13];
    const float* lnb_b    = (const float*)d_in[14];
    const float* Wb       = (const float*)d_in[15];
    const float* Wg       = (const float*)d_in[16];
    const float* Wo       = (const float*)d_in[17];
    const float* Ws_out   = (const float*)d_in[18];
    const float* bs_out   = (const float*)d_in[19];
    float* out = (float*)d_out;

    float* p_aln  = sym(g_aln);
    float* p_sln  = sym(g_sln);
    float* p_t1   = sym(g_t1);
    float* p_t2   = sym(g_t2);
    float* p_a2   = sym(g_a2);
    float* p_q    = sym(g_q);
    float* p_k    = sym(g_k);
    float* p_v    = sym(g_v);
    float* p_g    = sym(g_gbuf);
    float* p_gate = sym(g_gate);
    float* p_sc   = sym(g_scores);
    float* p_o    = sym(g_o);

    const int NEL = ROWS * CA;

    // pair bias first (independent of everything else)
    {
        dim3 g(II / 64, ROWS);
        pairbias_kernel<<<g, 256>>>(z_ij, beta_ij, lnb_w, lnb_b, Wb, p_sc);
    }

    // LayerNorms
    ln_kernel<<<ROWS, 256>>>(a_i, nullptr, nullptr, p_aln, CA);
    ln_kernel<<<ROWS, 256>>>(s_i, lns_w, lns_b, p_sln, CS);

    // AdaLN pair + output gate, all K=384, one batched launch
    {
        GemmBatch gb = {};
        gb.j[0] = { p_sln, Ws,     bs,      nullptr, p_t1,   0 };
        gb.j[1] = { p_sln, Wnb,    nullptr, nullptr, p_t2,   0 };
        gb.j[2] = { s_i,   Ws_out, bs_out,  nullptr, p_gate, 1 };
        dim3 g(CA / 64, ROWS / 128, 3);
        gemm_tc_kernel<<<g, 256>>>(gb, ROWS, CA, CS);
    }
    adaln_ew_kernel<<<(NEL + 255) / 256, 256>>>(p_t1, p_t2, p_aln, p_a2, NEL);

    // projections q,k,v,g (K=768)
    {
        GemmBatch gb = {};
        gb.j[0] = { p_a2, Wq, bq,      nullptr, p_q, 0 };
        gb.j[1] = { p_a2, Wk, nullptr, nullptr, p_k, 0 };
        gb.j[2] = { p_a2, Wv, nullptr, nullptr, p_v, 0 };
        gb.j[3] = { p_a2, Wg, nullptr, nullptr, p_g, 0 };
        dim3 g(HC / 64, ROWS / 128, 4);
        gemm_tc_kernel<<<g, 256>>>(gb, ROWS, HC, CA);
    }

    // scores += qk/sqrt(D)
    {
        dim3 g(II / 64, II / 64, BB * HH);
        qk_tc_kernel<<<g, 128>>>(p_q, p_k, p_sc);
    }

    // softmax + AV + gate (scalar, proven)
    {
        dim3 g(II / 16, BB * HH);
        softmax_av_kernel<<<g, 192>>>(p_sc, p_v, p_g, p_o);
    }

    // out = gate * (o @ Wo)
    {
        GemmBatch gb = {};
        gb.j[0] = { p_o, Wo, nullptr, p_gate, out, 0 };
        dim3 g(CA / 64, ROWS / 128, 1);
        gemm_tc_kernel<<<g, 256>>>(gb, ROWS, CA, HC);
    }
}